// round 10
// baseline (speedup 1.0000x reference)
#include <cuda_runtime.h>
#include <math.h>

#define BB 8
#define NN 2048
#define DD 1024
#define H1 128
#define FF 28
#define DK 64
#define NSTEPS 4
#define BN (BB*NN)

// ---- scratch (static device globals; no runtime allocation) ----
static __device__ float  g_H[BN*H1];
static __device__ float  g_V[BN*DK];
static __device__ float  g_Q[BN*DK];
static __device__ float  g_K[BN*DK];
static __device__ float  g_compat[(size_t)BB*NN*NN];  // lower triangle valid
static __device__ float  g_ccur[BN];
static __device__ float4 g_cpack[BN];                 // (c1,c2,c3,c4)
static __device__ float  g_Zinv[BN];
static __device__ float  g_AV[BN*DK];

// ============================================================
// K1: Y[16384,192] = X @ [W1|Wv]^T. 128x192 tile, 8x12 acc,
// double-buffered K-tile=16. 128 blocks (one wave).
// ============================================================
__global__ void __launch_bounds__(256) k1_gemm(const float* __restrict__ X,
        const float* __restrict__ w1, const float* __restrict__ b1,
        const float* __restrict__ wv) {
    __shared__ float Xs[2][16][132];
    __shared__ float Ws[2][16][200];
    const int t  = threadIdx.x;
    const int tx = t & 15, ty = t >> 4;
    const int r0 = blockIdx.x * 128;

    float acc[8][12];
    #pragma unroll
    for (int i = 0; i < 8; i++)
        #pragma unroll
        for (int j = 0; j < 12; j++) acc[i][j] = 0.f;

    #pragma unroll
    for (int i = 0; i < 8; i++) {
        int idx = t + i*256;  int r = idx >> 4, kk = idx & 15;
        Xs[0][kk][r] = X[(size_t)(r0+r)*DD + kk];
    }
    #pragma unroll
    for (int i = 0; i < 12; i++) {
        int idx = t + i*256;  int o = idx >> 4, kk = idx & 15;
        Ws[0][kk][o] = (o < H1) ? w1[o*DD + kk] : wv[(o-H1)*DD + kk];
    }
    __syncthreads();

    for (int kt = 0; kt < DD/16; kt++) {
        const int cur = kt & 1, nxt = cur ^ 1;
        float xr_st[8], wr_st[12];
        const bool more = (kt + 1 < DD/16);
        if (more) {
            int k0 = (kt+1)*16;
            #pragma unroll
            for (int i = 0; i < 8; i++) {
                int idx = t + i*256;  int r = idx >> 4, kk = idx & 15;
                xr_st[i] = X[(size_t)(r0+r)*DD + k0 + kk];
            }
            #pragma unroll
            for (int i = 0; i < 12; i++) {
                int idx = t + i*256;  int o = idx >> 4, kk = idx & 15;
                wr_st[i] = (o < H1) ? w1[o*DD + k0 + kk] : wv[(o-H1)*DD + k0 + kk];
            }
        }
        #pragma unroll
        for (int k = 0; k < 16; k++) {
            float4 xa = *reinterpret_cast<const float4*>(&Xs[cur][k][ty*4]);
            float4 xb = *reinterpret_cast<const float4*>(&Xs[cur][k][64 + ty*4]);
            float xr[8] = {xa.x,xa.y,xa.z,xa.w, xb.x,xb.y,xb.z,xb.w};
            float4 w0 = *reinterpret_cast<const float4*>(&Ws[cur][k][tx*4]);
            float4 w1v = *reinterpret_cast<const float4*>(&Ws[cur][k][64 + tx*4]);
            float4 w2v = *reinterpret_cast<const float4*>(&Ws[cur][k][128 + tx*4]);
            float wr[12] = {w0.x,w0.y,w0.z,w0.w, w1v.x,w1v.y,w1v.z,w1v.w,
                            w2v.x,w2v.y,w2v.z,w2v.w};
            #pragma unroll
            for (int i = 0; i < 8; i++)
                #pragma unroll
                for (int j = 0; j < 12; j++)
                    acc[i][j] = fmaf(xr[i], wr[j], acc[i][j]);
        }
        if (more) {
            #pragma unroll
            for (int i = 0; i < 8; i++) {
                int idx = t + i*256;  int r = idx >> 4, kk = idx & 15;
                Xs[nxt][kk][r] = xr_st[i];
            }
            #pragma unroll
            for (int i = 0; i < 12; i++) {
                int idx = t + i*256;  int o = idx >> 4, kk = idx & 15;
                Ws[nxt][kk][o] = wr_st[i];
            }
        }
        __syncthreads();
    }
    float4 b1a = *reinterpret_cast<const float4*>(&b1[tx*4]);
    float4 b1b = *reinterpret_cast<const float4*>(&b1[64 + tx*4]);
    float ba[8] = {b1a.x,b1a.y,b1a.z,b1a.w, b1b.x,b1b.y,b1b.z,b1b.w};
    #pragma unroll
    for (int i = 0; i < 8; i++) {
        int r = r0 + (i < 4 ? ty*4 + i : 64 + ty*4 + (i-4));
        float h[8];
        #pragma unroll
        for (int j = 0; j < 8; j++) {
            float v = acc[i][j] + ba[j];
            h[j] = 0.5f * v * (1.f + erff(v * 0.7071067811865476f));
        }
        *reinterpret_cast<float4*>(&g_H[(size_t)r*H1 + tx*4])      = make_float4(h[0],h[1],h[2],h[3]);
        *reinterpret_cast<float4*>(&g_H[(size_t)r*H1 + 64 + tx*4]) = make_float4(h[4],h[5],h[6],h[7]);
        *reinterpret_cast<float4*>(&g_V[(size_t)r*DK + tx*4]) =
            make_float4(acc[i][8], acc[i][9], acc[i][10], acc[i][11]);
    }
}

// ============================================================
// K2: features = sigmoid(H@W2^T+b2); Q/K; charge0; zero g_cpack
// ============================================================
__global__ void __launch_bounds__(256) k2_feat(const float* __restrict__ w2,
        const float* __restrict__ b2, const float* __restrict__ wq,
        const float* __restrict__ wk, const float* __restrict__ wc,
        const float* __restrict__ bc) {
    __shared__ float Hs[8][H1];
    __shared__ float Fs[8][FF];
    int warp = threadIdx.x >> 5, lane = threadIdx.x & 31;
    int row = blockIdx.x * 8 + warp;

    for (int k = lane; k < H1; k += 32) Hs[warp][k] = g_H[(size_t)row*H1 + k];
    __syncwarp();
    if (lane < FF) {
        float s = b2[lane];
        #pragma unroll 4
        for (int k = 0; k < H1; k++) s = fmaf(Hs[warp][k], w2[lane*H1 + k], s);
        Fs[warp][lane] = 1.f / (1.f + __expf(-s));
    }
    __syncwarp();
    #pragma unroll
    for (int half = 0; half < 2; half++) {
        int d = lane + half*32;
        float q = 0.f, kv = 0.f;
        #pragma unroll
        for (int j = 0; j < FF; j++) {
            float fv = Fs[warp][j];
            q  = fmaf(fv, wq[d*FF + j], q);
            kv = fmaf(fv, wk[d*FF + j], kv);
        }
        g_Q[(size_t)row*DK + d] = q;
        g_K[(size_t)row*DK + d] = kv;
    }
    if (lane == 0) {
        float s = bc[0];
        #pragma unroll
        for (int j = 0; j < FF; j++) s = fmaf(Fs[warp][j], wc[j], s);
        g_ccur[row] = 1.f / (1.f + __expf(-s));
        g_cpack[row] = make_float4(0.f, 0.f, 0.f, 0.f);
    }
}

// ============================================================
// K3: compat = Q@K^T/8.  128x128 tiles (triangle), 8x8 acc.
// ============================================================
__global__ void __launch_bounds__(256) k3_compat() {
    int tc = blockIdx.x, tr = blockIdx.y, b = blockIdx.z;
    if (tc > tr) return;
    __shared__ float Qs[32][132];
    __shared__ float Ks[32][132];
    int t = threadIdx.x, tx = t & 15, ty = t >> 4;
    int r0 = tr*128, c0 = tc*128;
    const float* Qb = g_Q + (size_t)b*NN*DK;
    const float* Kb = g_K + (size_t)b*NN*DK;

    float acc[8][8];
    #pragma unroll
    for (int i = 0; i < 8; i++)
        #pragma unroll
        for (int j = 0; j < 8; j++) acc[i][j] = 0.f;

    for (int kc = 0; kc < 2; kc++) {
        int kb0 = kc*32;
        #pragma unroll
        for (int i = 0; i < 16; i++) {
            int idx = t + i*256;
            int r = idx >> 5, kk = idx & 31;
            Qs[kk][r] = Qb[(size_t)(r0+r)*DK + kb0 + kk];
            Ks[kk][r] = Kb[(size_t)(c0+r)*DK + kb0 + kk];
        }
        __syncthreads();
        #pragma unroll
        for (int k = 0; k < 32; k++) {
            float4 qa = *reinterpret_cast<const float4*>(&Qs[k][ty*4]);
            float4 qb = *reinterpret_cast<const float4*>(&Qs[k][64 + ty*4]);
            float4 ka = *reinterpret_cast<const float4*>(&Ks[k][tx*4]);
            float4 kb = *reinterpret_cast<const float4*>(&Ks[k][64 + tx*4]);
            float xr[8] = {qa.x,qa.y,qa.z,qa.w, qb.x,qb.y,qb.z,qb.w};
            float wr[8] = {ka.x,ka.y,ka.z,ka.w, kb.x,kb.y,kb.z,kb.w};
            #pragma unroll
            for (int i = 0; i < 8; i++)
                #pragma unroll
                for (int j = 0; j < 8; j++)
                    acc[i][j] = fmaf(xr[i], wr[j], acc[i][j]);
        }
        __syncthreads();
    }
    float* Cb = g_compat + (size_t)b*NN*NN;
    #pragma unroll
    for (int i = 0; i < 8; i++) {
        int n = r0 + (i < 4 ? ty*4 + i : 64 + ty*4 + (i-4));
        *reinterpret_cast<float4*>(&Cb[(size_t)n*NN + c0 + tx*4]) =
            make_float4(acc[i][0]*0.125f, acc[i][1]*0.125f, acc[i][2]*0.125f, acc[i][3]*0.125f);
        *reinterpret_cast<float4*>(&Cb[(size_t)n*NN + c0 + 64 + tx*4]) =
            make_float4(acc[i][4]*0.125f, acc[i][5]*0.125f, acc[i][6]*0.125f, acc[i][7]*0.125f);
    }
}

// ============================================================
// kA (tiled): Zinv[n] = 1/Σ_{m<=n} exp(compat*(1+step*cp[n]·cp[m])).
// Block pairs row-tiles (x, 31-x): uniform 33 tile-iters.
// Thread (g=tid>>6, c=tid&63) covers rows r=g+4i, col m0+c.
// ============================================================
__global__ void __launch_bounds__(256) kA_Z(const float* __restrict__ step_p) {
    __shared__ float4 crp[64];
    __shared__ float sred[8][16];
    int b = blockIdx.y;
    int tid = threadIdx.x, c = tid & 63, g = tid >> 6;
    int lane = tid & 31, w = tid >> 5;
    float step = *step_p;
    const float* Cb = g_compat + (size_t)b*NN*NN;
    const float4* packb = g_cpack + b*NN;

    #pragma unroll
    for (int phase = 0; phase < 2; phase++) {
        int tr = phase ? 31 - (int)blockIdx.x : (int)blockIdx.x;
        int r0 = tr*64;
        if (tid < 64) crp[tid] = packb[r0 + tid];
        __syncthreads();
        float z[16];
        #pragma unroll
        for (int i = 0; i < 16; i++) z[i] = 0.f;

        for (int mt = 0; mt <= tr; mt++) {
            int m0 = mt*64;
            float4 cc = packb[m0 + c];
            if (mt < tr) {
                #pragma unroll
                for (int i = 0; i < 16; i++) {
                    int r = g + i*4;
                    float4 cr = crp[r];
                    float dot = cr.x*cc.x + cr.y*cc.y + cr.z*cc.z + cr.w*cc.w;
                    z[i] += __expf(Cb[(size_t)(r0+r)*NN + m0 + c] * fmaf(step, dot, 1.f));
                }
            } else {            // diagonal tile: only c <= r
                #pragma unroll
                for (int i = 0; i < 16; i++) {
                    int r = g + i*4;
                    if (c <= r) {
                        float4 cr = crp[r];
                        float dot = cr.x*cc.x + cr.y*cc.y + cr.z*cc.z + cr.w*cc.w;
                        z[i] += __expf(Cb[(size_t)(r0+r)*NN + m0 + c] * fmaf(step, dot, 1.f));
                    }
                }
            }
        }
        // reduce: warp covers 32 of the 64 cols for each of its 16 rows
        #pragma unroll
        for (int i = 0; i < 16; i++) {
            #pragma unroll
            for (int o = 16; o; o >>= 1)
                z[i] += __shfl_xor_sync(0xffffffffu, z[i], o);
        }
        if (lane == 0) {
            #pragma unroll
            for (int i = 0; i < 16; i++) sred[w][i] = z[i];
        }
        __syncthreads();
        if (tid < 64) {
            int g2 = tid & 3, i2 = tid >> 2;      // row r = g2 + 4*i2
            float val = sred[2*g2][i2] + sred[2*g2+1][i2];
            g_Zinv[b*NN + r0 + tid] = 1.f / val;
        }
        __syncthreads();   // protect crp/sred before next phase
    }
}

// ============================================================
// kB (tiled, step t): recv[m] = Σ_{n>=m} exp(l(n,m))·Zinv[n];
// charge update + cpack component t. Pairs col-tiles (x, 31-x).
// NOTE: cm is read at phase start (component t still 0), so the
// cross-block cpack write race is nullified (cm_t * cn_t = 0).
// ============================================================
__global__ void __launch_bounds__(256) kB_recv(int t, const float* __restrict__ step_p,
                                               const float* __restrict__ decay_p) {
    __shared__ float4 cps[64];
    __shared__ float  Zs[64];
    __shared__ float  part[4][64];
    int b = blockIdx.y;
    int tid = threadIdx.x, c = tid & 63, g = tid >> 6;
    float step = *step_p;
    const float* Cb = g_compat + (size_t)b*NN*NN;
    const float4* packb = g_cpack + b*NN;

    #pragma unroll
    for (int phase = 0; phase < 2; phase++) {
        int tc = phase ? 31 - (int)blockIdx.x : (int)blockIdx.x;
        int m0 = tc*64;
        int m = m0 + c;
        float4 cm = packb[m];
        float acc = 0.f;

        for (int mt = tc; mt < 32; mt++) {
            int n0 = mt*64;
            if (tid < 64) {
                cps[tid] = packb[n0 + tid];
                Zs[tid]  = g_Zinv[b*NN + n0 + tid];
            }
            __syncthreads();
            if (mt > tc) {
                #pragma unroll
                for (int i = 0; i < 16; i++) {
                    int r = g + i*4;
                    float4 cn = cps[r];
                    float dot = cm.x*cn.x + cm.y*cn.y + cm.z*cn.z + cm.w*cn.w;
                    float e = __expf(Cb[(size_t)(n0+r)*NN + m] * fmaf(step, dot, 1.f));
                    acc = fmaf(e, Zs[r], acc);
                }
            } else {            // diagonal tile: only r >= c
                #pragma unroll
                for (int i = 0; i < 16; i++) {
                    int r = g + i*4;
                    if (r >= c) {
                        float4 cn = cps[r];
                        float dot = cm.x*cn.x + cm.y*cn.y + cm.z*cn.z + cm.w*cn.w;
                        float e = __expf(Cb[(size_t)(n0+r)*NN + m] * fmaf(step, dot, 1.f));
                        acc = fmaf(e, Zs[r], acc);
                    }
                }
            }
            __syncthreads();    // protect cps/Zs before next tile
        }
        part[g][c] = acc;
        __syncthreads();
        if (tid < 64) {
            float r4 = part[0][c] + part[1][c] + part[2][c] + part[3][c];
            float decay = *decay_p;
            float cprev = g_ccur[b*NN + m];
            float sig = 1.f / (1.f + __expf(-(r4 - 1.f)));
            float cnew = cprev * (1.f - decay*sig);
            g_ccur[b*NN + m] = cnew;
            float4 p = cm;
            if      (t == 0) p.x = cnew;
            else if (t == 1) p.y = cnew;
            else if (t == 2) p.z = cnew;
            else             p.w = cnew;
            g_cpack[b*NN + m] = p;
        }
        __syncthreads();        // protect part before next phase
    }
}

// ============================================================
// K5: final attention, exp recomputed in-tile, Z fused.
// Pairs row-tiles (x, 31-x): uniform work, 128 blocks.
// ============================================================
__global__ void __launch_bounds__(256) k5_EV(const float* __restrict__ step_p) {
    __shared__ float Es[64][68];
    __shared__ float Vs[64][68];
    __shared__ float4 crp[64];
    int b = blockIdx.y;
    int t = threadIdx.x, tx = t & 15, ty = t >> 4;
    float step = *step_p;
    const float* Cb = g_compat + (size_t)b*NN*NN;
    const float* Vb = g_V + (size_t)b*NN*DK;
    const int cload = t & 63;

    #pragma unroll
    for (int phase = 0; phase < 2; phase++) {
        int tr = phase ? 31 - (int)blockIdx.x : (int)blockIdx.x;
        int r0 = tr * 64;
        if (t < 64) crp[t] = g_cpack[b*NN + r0 + t];
        __syncthreads();

        float acc[4][4];
        #pragma unroll
        for (int i = 0; i < 4; i++)
            #pragma unroll
            for (int j = 0; j < 4; j++) acc[i][j] = 0.f;
        float zrun[4] = {0.f, 0.f, 0.f, 0.f};

        for (int mt = 0; mt <= tr; mt++) {
            int m0 = mt * 64;
            bool diag = (mt == tr);
            float4 cc = g_cpack[b*NN + m0 + cload];
            #pragma unroll
            for (int i = 0; i < 16; i++) {
                int idx = t + i*256;
                int r = idx >> 6, c = idx & 63;  // c == cload
                float4 cr = crp[r];
                float dot = cr.x*cc.x + cr.y*cc.y + cr.z*cc.z + cr.w*cc.w;
                float e;
                if (diag && c > r) e = 0.f;
                else e = __expf(Cb[(size_t)(r0+r)*NN + m0 + c] * fmaf(step, dot, 1.f));
                Es[r][c] = e;
                Vs[r][c] = Vb[(size_t)(m0+r)*DK + c];
            }
            __syncthreads();
            #pragma unroll 4
            for (int k = 0; k < 64; k += 4) {
                float4 e0 = *reinterpret_cast<const float4*>(&Es[ty*4+0][k]);
                float4 e1 = *reinterpret_cast<const float4*>(&Es[ty*4+1][k]);
                float4 e2 = *reinterpret_cast<const float4*>(&Es[ty*4+2][k]);
                float4 e3 = *reinterpret_cast<const float4*>(&Es[ty*4+3][k]);
                float er[4][4] = {{e0.x,e0.y,e0.z,e0.w},{e1.x,e1.y,e1.z,e1.w},
                                  {e2.x,e2.y,e2.z,e2.w},{e3.x,e3.y,e3.z,e3.w}};
                #pragma unroll
                for (int i = 0; i < 4; i++)
                    zrun[i] += (er[i][0] + er[i][1]) + (er[i][2] + er[i][3]);
                #pragma unroll
                for (int q = 0; q < 4; q++) {
                    float4 v = *reinterpret_cast<const float4*>(&Vs[k+q][tx*4]);
                    float vr[4] = {v.x, v.y, v.z, v.w};
                    #pragma unroll
                    for (int i = 0; i < 4; i++)
                        #pragma unroll
                        for (int j = 0; j < 4; j++)
                            acc[i][j] = fmaf(er[i][q], vr[j], acc[i][j]);
                }
            }
            __syncthreads();
        }
        #pragma unroll
        for (int i = 0; i < 4; i++) {
            int row = b*NN + r0 + ty*4 + i;
            float zi = 1.f / zrun[i];
            *reinterpret_cast<float4*>(&g_AV[(size_t)row*DK + tx*4]) =
                make_float4(acc[i][0]*zi, acc[i][1]*zi, acc[i][2]*zi, acc[i][3]*zi);
        }
        __syncthreads();        // protect crp before next phase
    }
}

// ============================================================
// K6: out = alpha * (AV @ wo^T). 128x128 tiles, 8x8 acc.
// ============================================================
__global__ void __launch_bounds__(256) k6_out(const float* __restrict__ wo,
        const float* __restrict__ mix_p, float* __restrict__ out) {
    __shared__ float As[32][132];
    __shared__ float Ws[32][132];
    int t = threadIdx.x, tx = t & 15, ty = t >> 4;
    int r0 = blockIdx.y * 128, c0 = blockIdx.x * 128;

    float acc[8][8];
    #pragma unroll
    for (int i = 0; i < 8; i++)
        #pragma unroll
        for (int j = 0; j < 8; j++) acc[i][j] = 0.f;

    for (int kc = 0; kc < 2; kc++) {
        int kb0 = kc*32;
        #pragma unroll
        for (int i = 0; i < 16; i++) {
            int idx = t + i*256;
            int r = idx >> 5, kk = idx & 31;
            As[kk][r] = g_AV[(size_t)(r0+r)*DK + kb0 + kk];
            Ws[kk][r] = wo[(size_t)(c0+r)*DK + kb0 + kk];
        }
        __syncthreads();
        #pragma unroll
        for (int k = 0; k < 32; k++) {
            float4 aa = *reinterpret_cast<const float4*>(&As[k][ty*4]);
            float4 ab = *reinterpret_cast<const float4*>(&As[k][64 + ty*4]);
            float4 wa = *reinterpret_cast<const float4*>(&Ws[k][tx*4]);
            float4 wb = *reinterpret_cast<const float4*>(&Ws[k][64 + tx*4]);
            float xr[8] = {aa.x,aa.y,aa.z,aa.w, ab.x,ab.y,ab.z,ab.w};
            float wr[8] = {wa.x,wa.y,wa.z,wa.w, wb.x,wb.y,wb.z,wb.w};
            #pragma unroll
            for (int i = 0; i < 8; i++)
                #pragma unroll
                for (int j = 0; j < 8; j++)
                    acc[i][j] = fmaf(xr[i], wr[j], acc[i][j]);
        }
        __syncthreads();
    }
    float alpha = 0.2f / (1.f + __expf(-mix_p[0]));
    #pragma unroll
    for (int i = 0; i < 8; i++) {
        int r = r0 + (i < 4 ? ty*4 + i : 64 + ty*4 + (i-4));
        *reinterpret_cast<float4*>(&out[(size_t)r*DD + c0 + tx*4]) =
            make_float4(acc[i][0]*alpha, acc[i][1]*alpha, acc[i][2]*alpha, acc[i][3]*alpha);
        *reinterpret_cast<float4*>(&out[(size_t)r*DD + c0 + 64 + tx*4]) =
            make_float4(acc[i][4]*alpha, acc[i][5]*alpha, acc[i][6]*alpha, acc[i][7]*alpha);
    }
}

// ============================================================
extern "C" void kernel_launch(void* const* d_in, const int* in_sizes, int n_in,
                              void* d_out, int out_size) {
    const float* X       = (const float*)d_in[0];
    const float* w1      = (const float*)d_in[2];
    const float* b1      = (const float*)d_in[3];
    const float* w2      = (const float*)d_in[4];
    const float* b2      = (const float*)d_in[5];
    const float* wq      = (const float*)d_in[6];
    const float* wk      = (const float*)d_in[7];
    const float* wc      = (const float*)d_in[8];
    const float* bc      = (const float*)d_in[9];
    const float* step_p  = (const float*)d_in[10];
    const float* decay_p = (const float*)d_in[11];
    const float* wv      = (const float*)d_in[12];
    const float* wo      = (const float*)d_in[13];
    const float* mix_p   = (const float*)d_in[14];
    float* out = (float*)d_out;

    k1_gemm<<<BN/128, 256>>>(X, w1, b1, wv);
    k2_feat<<<BN/8, 256>>>(w2, b2, wq, wk, wc, bc);
    k3_compat<<<dim3(NN/128, NN/128, BB), 256>>>();
    for (int t = 0; t < NSTEPS; t++) {
        kA_Z<<<dim3(16, BB), 256>>>(step_p);
        kB_recv<<<dim3(16, BB), 256>>>(t, step_p, decay_p);
    }
    k5_EV<<<dim3(16, BB), 256>>>(step_p);
    k6_out<<<dim3(DD/128, BN/128), 256>>>(wo, mix_p, out);
}

// round 11
// speedup vs baseline: 1.2337x; 1.2337x over previous
#include <cuda_runtime.h>
#include <math.h>

#define BB 8
#define NN 2048
#define DD 1024
#define H1 128
#define FF 28
#define DK 64
#define NSTEPS 4
#define NSEG 8
#define BN (BB*NN)

// ---- scratch (static device globals; no runtime allocation) ----
static __device__ float  g_H[BN*H1];
static __device__ float  g_V[BN*DK];
static __device__ float  g_Q[BN*DK];
static __device__ float  g_K[BN*DK];
static __device__ float  g_compat[(size_t)BB*NN*NN];  // lower triangle valid
static __device__ float  g_ccur[BN];
static __device__ float4 g_cpack[BN];                 // (c1,c2,c3,c4)
static __device__ float  g_Zpart[NSEG][BN];           // partial row sums of exp
static __device__ float  g_Rpart[NSEG][BN];           // partial col sums (recv)
static __device__ float  g_AV[BN*DK];

// ============================================================
// K1: Y[16384,192] = X @ [W1|Wv]^T. 128x192 tile, 8x12 acc,
// double-buffered K-tile=16. 128 blocks.
// ============================================================
__global__ void __launch_bounds__(256) k1_gemm(const float* __restrict__ X,
        const float* __restrict__ w1, const float* __restrict__ b1,
        const float* __restrict__ wv) {
    __shared__ float Xs[2][16][132];
    __shared__ float Ws[2][16][200];
    const int t  = threadIdx.x;
    const int tx = t & 15, ty = t >> 4;
    const int r0 = blockIdx.x * 128;

    float acc[8][12];
    #pragma unroll
    for (int i = 0; i < 8; i++)
        #pragma unroll
        for (int j = 0; j < 12; j++) acc[i][j] = 0.f;

    #pragma unroll
    for (int i = 0; i < 8; i++) {
        int idx = t + i*256;  int r = idx >> 4, kk = idx & 15;
        Xs[0][kk][r] = X[(size_t)(r0+r)*DD + kk];
    }
    #pragma unroll
    for (int i = 0; i < 12; i++) {
        int idx = t + i*256;  int o = idx >> 4, kk = idx & 15;
        Ws[0][kk][o] = (o < H1) ? w1[o*DD + kk] : wv[(o-H1)*DD + kk];
    }
    __syncthreads();

    for (int kt = 0; kt < DD/16; kt++) {
        const int cur = kt & 1, nxt = cur ^ 1;
        float xr_st[8], wr_st[12];
        const bool more = (kt + 1 < DD/16);
        if (more) {
            int k0 = (kt+1)*16;
            #pragma unroll
            for (int i = 0; i < 8; i++) {
                int idx = t + i*256;  int r = idx >> 4, kk = idx & 15;
                xr_st[i] = X[(size_t)(r0+r)*DD + k0 + kk];
            }
            #pragma unroll
            for (int i = 0; i < 12; i++) {
                int idx = t + i*256;  int o = idx >> 4, kk = idx & 15;
                wr_st[i] = (o < H1) ? w1[o*DD + k0 + kk] : wv[(o-H1)*DD + k0 + kk];
            }
        }
        #pragma unroll
        for (int k = 0; k < 16; k++) {
            float4 xa = *reinterpret_cast<const float4*>(&Xs[cur][k][ty*4]);
            float4 xb = *reinterpret_cast<const float4*>(&Xs[cur][k][64 + ty*4]);
            float xr[8] = {xa.x,xa.y,xa.z,xa.w, xb.x,xb.y,xb.z,xb.w};
            float4 w0 = *reinterpret_cast<const float4*>(&Ws[cur][k][tx*4]);
            float4 w1v = *reinterpret_cast<const float4*>(&Ws[cur][k][64 + tx*4]);
            float4 w2v = *reinterpret_cast<const float4*>(&Ws[cur][k][128 + tx*4]);
            float wr[12] = {w0.x,w0.y,w0.z,w0.w, w1v.x,w1v.y,w1v.z,w1v.w,
                            w2v.x,w2v.y,w2v.z,w2v.w};
            #pragma unroll
            for (int i = 0; i < 8; i++)
                #pragma unroll
                for (int j = 0; j < 12; j++)
                    acc[i][j] = fmaf(xr[i], wr[j], acc[i][j]);
        }
        if (more) {
            #pragma unroll
            for (int i = 0; i < 8; i++) {
                int idx = t + i*256;  int r = idx >> 4, kk = idx & 15;
                Xs[nxt][kk][r] = xr_st[i];
            }
            #pragma unroll
            for (int i = 0; i < 12; i++) {
                int idx = t + i*256;  int o = idx >> 4, kk = idx & 15;
                Ws[nxt][kk][o] = wr_st[i];
            }
        }
        __syncthreads();
    }
    float4 b1a = *reinterpret_cast<const float4*>(&b1[tx*4]);
    float4 b1b = *reinterpret_cast<const float4*>(&b1[64 + tx*4]);
    float ba[8] = {b1a.x,b1a.y,b1a.z,b1a.w, b1b.x,b1b.y,b1b.z,b1b.w};
    #pragma unroll
    for (int i = 0; i < 8; i++) {
        int r = r0 + (i < 4 ? ty*4 + i : 64 + ty*4 + (i-4));
        float h[8];
        #pragma unroll
        for (int j = 0; j < 8; j++) {
            float v = acc[i][j] + ba[j];
            h[j] = 0.5f * v * (1.f + erff(v * 0.7071067811865476f));
        }
        *reinterpret_cast<float4*>(&g_H[(size_t)r*H1 + tx*4])      = make_float4(h[0],h[1],h[2],h[3]);
        *reinterpret_cast<float4*>(&g_H[(size_t)r*H1 + 64 + tx*4]) = make_float4(h[4],h[5],h[6],h[7]);
        *reinterpret_cast<float4*>(&g_V[(size_t)r*DK + tx*4]) =
            make_float4(acc[i][8], acc[i][9], acc[i][10], acc[i][11]);
    }
}

// ============================================================
// K2: features = sigmoid(H@W2^T+b2); Q/K; charge0; zero g_cpack
// ============================================================
__global__ void __launch_bounds__(256) k2_feat(const float* __restrict__ w2,
        const float* __restrict__ b2, const float* __restrict__ wq,
        const float* __restrict__ wk, const float* __restrict__ wc,
        const float* __restrict__ bc) {
    __shared__ float Hs[8][H1];
    __shared__ float Fs[8][FF];
    int warp = threadIdx.x >> 5, lane = threadIdx.x & 31;
    int row = blockIdx.x * 8 + warp;

    for (int k = lane; k < H1; k += 32) Hs[warp][k] = g_H[(size_t)row*H1 + k];
    __syncwarp();
    if (lane < FF) {
        float s = b2[lane];
        #pragma unroll 4
        for (int k = 0; k < H1; k++) s = fmaf(Hs[warp][k], w2[lane*H1 + k], s);
        Fs[warp][lane] = 1.f / (1.f + __expf(-s));
    }
    __syncwarp();
    #pragma unroll
    for (int half = 0; half < 2; half++) {
        int d = lane + half*32;
        float q = 0.f, kv = 0.f;
        #pragma unroll
        for (int j = 0; j < FF; j++) {
            float fv = Fs[warp][j];
            q  = fmaf(fv, wq[d*FF + j], q);
            kv = fmaf(fv, wk[d*FF + j], kv);
        }
        g_Q[(size_t)row*DK + d] = q;
        g_K[(size_t)row*DK + d] = kv;
    }
    if (lane == 0) {
        float s = bc[0];
        #pragma unroll
        for (int j = 0; j < FF; j++) s = fmaf(Fs[warp][j], wc[j], s);
        g_ccur[row] = 1.f / (1.f + __expf(-s));
        g_cpack[row] = make_float4(0.f, 0.f, 0.f, 0.f);
    }
}

// ============================================================
// K3: compat = Q@K^T/8.  128x128 tiles (triangle), 8x8 acc.
// ============================================================
__global__ void __launch_bounds__(256) k3_compat() {
    int tc = blockIdx.x, tr = blockIdx.y, b = blockIdx.z;
    if (tc > tr) return;
    __shared__ float Qs[32][132];
    __shared__ float Ks[32][132];
    int t = threadIdx.x, tx = t & 15, ty = t >> 4;
    int r0 = tr*128, c0 = tc*128;
    const float* Qb = g_Q + (size_t)b*NN*DK;
    const float* Kb = g_K + (size_t)b*NN*DK;

    float acc[8][8];
    #pragma unroll
    for (int i = 0; i < 8; i++)
        #pragma unroll
        for (int j = 0; j < 8; j++) acc[i][j] = 0.f;

    for (int kc = 0; kc < 2; kc++) {
        int kb0 = kc*32;
        #pragma unroll
        for (int i = 0; i < 16; i++) {
            int idx = t + i*256;
            int r = idx >> 5, kk = idx & 31;
            Qs[kk][r] = Qb[(size_t)(r0+r)*DK + kb0 + kk];
            Ks[kk][r] = Kb[(size_t)(c0+r)*DK + kb0 + kk];
        }
        __syncthreads();
        #pragma unroll
        for (int k = 0; k < 32; k++) {
            float4 qa = *reinterpret_cast<const float4*>(&Qs[k][ty*4]);
            float4 qb = *reinterpret_cast<const float4*>(&Qs[k][64 + ty*4]);
            float4 ka = *reinterpret_cast<const float4*>(&Ks[k][tx*4]);
            float4 kb = *reinterpret_cast<const float4*>(&Ks[k][64 + tx*4]);
            float xr[8] = {qa.x,qa.y,qa.z,qa.w, qb.x,qb.y,qb.z,qb.w};
            float wr[8] = {ka.x,ka.y,ka.z,ka.w, kb.x,kb.y,kb.z,kb.w};
            #pragma unroll
            for (int i = 0; i < 8; i++)
                #pragma unroll
                for (int j = 0; j < 8; j++)
                    acc[i][j] = fmaf(xr[i], wr[j], acc[i][j]);
        }
        __syncthreads();
    }
    float* Cb = g_compat + (size_t)b*NN*NN;
    #pragma unroll
    for (int i = 0; i < 8; i++) {
        int n = r0 + (i < 4 ? ty*4 + i : 64 + ty*4 + (i-4));
        *reinterpret_cast<float4*>(&Cb[(size_t)n*NN + c0 + tx*4]) =
            make_float4(acc[i][0]*0.125f, acc[i][1]*0.125f, acc[i][2]*0.125f, acc[i][3]*0.125f);
        *reinterpret_cast<float4*>(&Cb[(size_t)n*NN + c0 + 64 + tx*4]) =
            make_float4(acc[i][4]*0.125f, acc[i][5]*0.125f, acc[i][6]*0.125f, acc[i][7]*0.125f);
    }
}

// ============================================================
// kA_part: partial row sums of exp(compat*(1+step*cp[n]·cp[m])).
// Block (p, seg, b): row-tiles p and 31-p (pairing), col-tiles
// mt = seg, seg+8, ... Writes g_Zpart[seg][row]. 1024 blocks.
// ============================================================
__global__ void __launch_bounds__(256) kA_part(const float* __restrict__ step_p) {
    __shared__ float4 crp[64];
    __shared__ float sred[8][16];
    int b = blockIdx.z, seg = blockIdx.y;
    int tid = threadIdx.x, c = tid & 63, g = tid >> 6;
    int lane = tid & 31, w = tid >> 5;
    float step = *step_p;
    const float* Cb = g_compat + (size_t)b*NN*NN;
    const float4* packb = g_cpack + b*NN;

    #pragma unroll
    for (int phase = 0; phase < 2; phase++) {
        int tr = phase ? 31 - (int)blockIdx.x : (int)blockIdx.x;
        int r0 = tr*64;
        if (tid < 64) crp[tid] = packb[r0 + tid];
        __syncthreads();
        float z[16];
        #pragma unroll
        for (int i = 0; i < 16; i++) z[i] = 0.f;

        for (int mt = seg; mt <= tr; mt += NSEG) {
            int m0 = mt*64;
            float4 cc = packb[m0 + c];
            if (mt < tr) {
                #pragma unroll
                for (int i = 0; i < 16; i++) {
                    int r = g + i*4;
                    float4 cr = crp[r];
                    float dot = cr.x*cc.x + cr.y*cc.y + cr.z*cc.z + cr.w*cc.w;
                    z[i] += __expf(Cb[(size_t)(r0+r)*NN + m0 + c] * fmaf(step, dot, 1.f));
                }
            } else {            // diagonal tile: only c <= r
                #pragma unroll
                for (int i = 0; i < 16; i++) {
                    int r = g + i*4;
                    if (c <= r) {
                        float4 cr = crp[r];
                        float dot = cr.x*cc.x + cr.y*cc.y + cr.z*cc.z + cr.w*cc.w;
                        z[i] += __expf(Cb[(size_t)(r0+r)*NN + m0 + c] * fmaf(step, dot, 1.f));
                    }
                }
            }
        }
        #pragma unroll
        for (int i = 0; i < 16; i++) {
            #pragma unroll
            for (int o = 16; o; o >>= 1)
                z[i] += __shfl_xor_sync(0xffffffffu, z[i], o);
        }
        if (lane == 0) {
            #pragma unroll
            for (int i = 0; i < 16; i++) sred[w][i] = z[i];
        }
        __syncthreads();
        if (tid < 64) {
            int g2 = tid & 3, i2 = tid >> 2;      // row = g2 + 4*i2
            g_Zpart[seg][b*NN + r0 + tid] = sred[2*g2][i2] + sred[2*g2+1][i2];
        }
        __syncthreads();   // protect crp/sred before next phase
    }
}

// ============================================================
// kB_part: partial recv[m] = Σ_{n>=m} exp(l)·Zinv[n] over this
// segment's n-tiles; Zinv = 1/Σ_seg Zpart. Writes g_Rpart.
// ============================================================
__global__ void __launch_bounds__(256) kB_part(const float* __restrict__ step_p) {
    __shared__ float4 cps[64];
    __shared__ float  Zs[64];
    __shared__ float  part[4][64];
    int b = blockIdx.z, seg = blockIdx.y;
    int tid = threadIdx.x, c = tid & 63, g = tid >> 6;
    float step = *step_p;
    const float* Cb = g_compat + (size_t)b*NN*NN;
    const float4* packb = g_cpack + b*NN;

    #pragma unroll
    for (int phase = 0; phase < 2; phase++) {
        int tc = phase ? 31 - (int)blockIdx.x : (int)blockIdx.x;
        int m0 = tc*64;
        int m = m0 + c;
        float4 cm = packb[m];
        float acc = 0.f;

        for (int mt = tc + seg; mt < 32; mt += NSEG) {
            int n0 = mt*64;
            if (tid < 64) {
                cps[tid] = packb[n0 + tid];
                float s = 0.f;
                #pragma unroll
                for (int q = 0; q < NSEG; q++) s += g_Zpart[q][b*NN + n0 + tid];
                Zs[tid] = 1.f / s;
            }
            __syncthreads();
            if (mt > tc) {
                #pragma unroll
                for (int i = 0; i < 16; i++) {
                    int r = g + i*4;
                    float4 cn = cps[r];
                    float dot = cm.x*cn.x + cm.y*cn.y + cm.z*cn.z + cm.w*cn.w;
                    float e = __expf(Cb[(size_t)(n0+r)*NN + m] * fmaf(step, dot, 1.f));
                    acc = fmaf(e, Zs[r], acc);
                }
            } else {            // diagonal tile: only r >= c
                #pragma unroll
                for (int i = 0; i < 16; i++) {
                    int r = g + i*4;
                    if (r >= c) {
                        float4 cn = cps[r];
                        float dot = cm.x*cn.x + cm.y*cn.y + cm.z*cn.z + cm.w*cn.w;
                        float e = __expf(Cb[(size_t)(n0+r)*NN + m] * fmaf(step, dot, 1.f));
                        acc = fmaf(e, Zs[r], acc);
                    }
                }
            }
            __syncthreads();    // protect cps/Zs before next tile
        }
        part[g][c] = acc;
        __syncthreads();
        if (tid < 64)
            g_Rpart[seg][b*NN + m] = part[0][c] + part[1][c] + part[2][c] + part[3][c];
        __syncthreads();        // protect part before next phase
    }
}

// ============================================================
// kB2 (tiny): recv = Σ_seg Rpart; charge update; cpack comp t.
// Sole writer of ccur/cpack -> no races anywhere.
// ============================================================
__global__ void __launch_bounds__(256) kB2(int t, const float* __restrict__ decay_p) {
    int idx = blockIdx.x*256 + threadIdx.x;
    float r = 0.f;
    #pragma unroll
    for (int q = 0; q < NSEG; q++) r += g_Rpart[q][idx];
    float decay = *decay_p;
    float cprev = g_ccur[idx];
    float sig = 1.f / (1.f + __expf(-(r - 1.f)));
    float cnew = cprev * (1.f - decay*sig);
    g_ccur[idx] = cnew;
    float4 p = g_cpack[idx];
    if      (t == 0) p.x = cnew;
    else if (t == 1) p.y = cnew;
    else if (t == 2) p.z = cnew;
    else             p.w = cnew;
    g_cpack[idx] = p;
}

// ============================================================
// K5: final attention, exp recomputed in-tile, Z fused (zrun).
// Grid (32, BB) — R9-measured configuration.
// ============================================================
__global__ void __launch_bounds__(256) k5_EV(const float* __restrict__ step_p) {
    __shared__ float Es[64][68];
    __shared__ float Vs[64][68];
    __shared__ float4 crp[64];
    int b = blockIdx.y;
    int tr = blockIdx.x;
    int r0 = tr * 64;
    int t = threadIdx.x, tx = t & 15, ty = t >> 4;
    float step = *step_p;

    if (t < 64) crp[t] = g_cpack[b*NN + r0 + t];

    float acc[4][4];
    #pragma unroll
    for (int i = 0; i < 4; i++)
        #pragma unroll
        for (int j = 0; j < 4; j++) acc[i][j] = 0.f;
    float zrun[4] = {0.f, 0.f, 0.f, 0.f};

    const float* Cb = g_compat + (size_t)b*NN*NN;
    const float* Vb = g_V + (size_t)b*NN*DK;
    __syncthreads();

    const int cload = t & 63;
    for (int mt = 0; mt <= tr; mt++) {
        int m0 = mt * 64;
        bool diag = (mt == tr);
        float4 cc = g_cpack[b*NN + m0 + cload];
        #pragma unroll
        for (int i = 0; i < 16; i++) {
            int idx = t + i*256;
            int r = idx >> 6, c = idx & 63;
            float4 cr = crp[r];
            float dot = cr.x*cc.x + cr.y*cc.y + cr.z*cc.z + cr.w*cc.w;
            float e;
            if (diag && c > r) e = 0.f;
            else e = __expf(Cb[(size_t)(r0+r)*NN + m0 + c] * fmaf(step, dot, 1.f));
            Es[r][c] = e;
            Vs[r][c] = Vb[(size_t)(m0+r)*DK + c];
        }
        __syncthreads();
        #pragma unroll 4
        for (int k = 0; k < 64; k += 4) {
            float4 e0 = *reinterpret_cast<const float4*>(&Es[ty*4+0][k]);
            float4 e1 = *reinterpret_cast<const float4*>(&Es[ty*4+1][k]);
            float4 e2 = *reinterpret_cast<const float4*>(&Es[ty*4+2][k]);
            float4 e3 = *reinterpret_cast<const float4*>(&Es[ty*4+3][k]);
            float er[4][4] = {{e0.x,e0.y,e0.z,e0.w},{e1.x,e1.y,e1.z,e1.w},
                              {e2.x,e2.y,e2.z,e2.w},{e3.x,e3.y,e3.z,e3.w}};
            #pragma unroll
            for (int i = 0; i < 4; i++)
                zrun[i] += (er[i][0] + er[i][1]) + (er[i][2] + er[i][3]);
            #pragma unroll
            for (int q = 0; q < 4; q++) {
                float4 v = *reinterpret_cast<const float4*>(&Vs[k+q][tx*4]);
                float vr[4] = {v.x, v.y, v.z, v.w};
                #pragma unroll
                for (int i = 0; i < 4; i++)
                    #pragma unroll
                    for (int j = 0; j < 4; j++)
                        acc[i][j] = fmaf(er[i][q], vr[j], acc[i][j]);
            }
        }
        __syncthreads();
    }
    #pragma unroll
    for (int i = 0; i < 4; i++) {
        int row = b*NN + r0 + ty*4 + i;
        float zi = 1.f / zrun[i];
        *reinterpret_cast<float4*>(&g_AV[(size_t)row*DK + tx*4]) =
            make_float4(acc[i][0]*zi, acc[i][1]*zi, acc[i][2]*zi, acc[i][3]*zi);
    }
}

// ============================================================
// K6: out = alpha * (AV @ wo^T). 128x128 tiles, 8x8 acc.
// ============================================================
__global__ void __launch_bounds__(256) k6_out(const float* __restrict__ wo,
        const float* __restrict__ mix_p, float* __restrict__ out) {
    __shared__ float As[32][132];
    __shared__ float Ws[32][132];
    int t = threadIdx.x, tx = t & 15, ty = t >> 4;
    int r0 = blockIdx.y * 128, c0 = blockIdx.x * 128;

    float acc[8][8];
    #pragma unroll
    for (int i = 0; i < 8; i++)
        #pragma unroll
        for (int j = 0; j < 8; j++) acc[i][j] = 0.f;

    for (int kc = 0; kc < 2; kc++) {
        int kb0 = kc*32;
        #pragma unroll
        for (int i = 0; i < 16; i++) {
            int idx = t + i*256;
            int r = idx >> 5, kk = idx & 31;
            As[kk][r] = g_AV[(size_t)(r0+r)*DK + kb0 + kk];
            Ws[kk][r] = wo[(size_t)(c0+r)*DK + kb0 + kk];
        }
        __syncthreads();
        #pragma unroll
        for (int k = 0; k < 32; k++) {
            float4 aa = *reinterpret_cast<const float4*>(&As[k][ty*4]);
            float4 ab = *reinterpret_cast<const float4*>(&As[k][64 + ty*4]);
            float4 wa = *reinterpret_cast<const float4*>(&Ws[k][tx*4]);
            float4 wb = *reinterpret_cast<const float4*>(&Ws[k][64 + tx*4]);
            float xr[8] = {aa.x,aa.y,aa.z,aa.w, ab.x,ab.y,ab.z,ab.w};
            float wr[8] = {wa.x,wa.y,wa.z,wa.w, wb.x,wb.y,wb.z,wb.w};
            #pragma unroll
            for (int i = 0; i < 8; i++)
                #pragma unroll
                for (int j = 0; j < 8; j++)
                    acc[i][j] = fmaf(xr[i], wr[j], acc[i][j]);
        }
        __syncthreads();
    }
    float alpha = 0.2f / (1.f + __expf(-mix_p[0]));
    #pragma unroll
    for (int i = 0; i < 8; i++) {
        int r = r0 + (i < 4 ? ty*4 + i : 64 + ty*4 + (i-4));
        *reinterpret_cast<float4*>(&out[(size_t)r*DD + c0 + tx*4]) =
            make_float4(acc[i][0]*alpha, acc[i][1]*alpha, acc[i][2]*alpha, acc[i][3]*alpha);
        *reinterpret_cast<float4*>(&out[(size_t)r*DD + c0 + 64 + tx*4]) =
            make_float4(acc[i][4]*alpha, acc[i][5]*alpha, acc[i][6]*alpha, acc[i][7]*alpha);
    }
}

// ============================================================
extern "C" void kernel_launch(void* const* d_in, const int* in_sizes, int n_in,
                              void* d_out, int out_size) {
    const float* X       = (const float*)d_in[0];
    const float* w1      = (const float*)d_in[2];
    const float* b1      = (const float*)d_in[3];
    const float* w2      = (const float*)d_in[4];
    const float* b2      = (const float*)d_in[5];
    const float* wq      = (const float*)d_in[6];
    const float* wk      = (const float*)d_in[7];
    const float* wc      = (const float*)d_in[8];
    const float* bc      = (const float*)d_in[9];
    const float* step_p  = (const float*)d_in[10];
    const float* decay_p = (const float*)d_in[11];
    const float* wv      = (const float*)d_in[12];
    const float* wo      = (const float*)d_in[13];
    const float* mix_p   = (const float*)d_in[14];
    float* out = (float*)d_out;

    k1_gemm<<<BN/128, 256>>>(X, w1, b1, wv);
    k2_feat<<<BN/8, 256>>>(w2, b2, wq, wk, wc, bc);
    k3_compat<<<dim3(NN/128, NN/128, BB), 256>>>();
    for (int t = 0; t < NSTEPS; t++) {
        kA_part<<<dim3(16, NSEG, BB), 256>>>(step_p);
        kB_part<<<dim3(16, NSEG, BB), 256>>>(step_p);
        kB2<<<BN/256, 256>>>(t, decay_p);
    }
    k5_EV<<<dim3(NN/64, BB), 256>>>(step_p);
    k6_out<<<dim3(DD/128, BN/128), 256>>>(wo, mix_p, out);
}

// round 12
// speedup vs baseline: 1.2393x; 1.0045x over previous
#include <cuda_runtime.h>
#include <math.h>

#define BB 8
#define NN 2048
#define DD 1024
#define H1 128
#define FF 28
#define DK 64
#define NSTEPS 4
#define NSEG 8
#define BN (BB*NN)

// ---- scratch (static device globals; no runtime allocation) ----
static __device__ float  g_H[BN*H1];
static __device__ float  g_V[BN*DK];
static __device__ float  g_Q[BN*DK];
static __device__ float  g_K[BN*DK];
static __device__ float  g_compat[(size_t)BB*NN*NN];  // lower triangle valid
static __device__ float  g_ccur[BN];
static __device__ float4 g_cpack[BN];                 // (c1,c2,c3,c4)
static __device__ float  g_Zpart[NSEG][BN];           // partial row sums of exp
static __device__ float  g_Rpart[NSEG][BN];           // partial col sums (recv)
static __device__ float  g_AV[BN*DK];

// ============================================================
// K1: Y[16384,192] = X @ [W1|Wv]^T. 128x192 tile, 8x12 acc,
// double-buffered K-tile=16. 128 blocks.
// ============================================================
__global__ void __launch_bounds__(256) k1_gemm(const float* __restrict__ X,
        const float* __restrict__ w1, const float* __restrict__ b1,
        const float* __restrict__ wv) {
    __shared__ float Xs[2][16][132];
    __shared__ float Ws[2][16][200];
    const int t  = threadIdx.x;
    const int tx = t & 15, ty = t >> 4;
    const int r0 = blockIdx.x * 128;

    float acc[8][12];
    #pragma unroll
    for (int i = 0; i < 8; i++)
        #pragma unroll
        for (int j = 0; j < 12; j++) acc[i][j] = 0.f;

    #pragma unroll
    for (int i = 0; i < 8; i++) {
        int idx = t + i*256;  int r = idx >> 4, kk = idx & 15;
        Xs[0][kk][r] = X[(size_t)(r0+r)*DD + kk];
    }
    #pragma unroll
    for (int i = 0; i < 12; i++) {
        int idx = t + i*256;  int o = idx >> 4, kk = idx & 15;
        Ws[0][kk][o] = (o < H1) ? w1[o*DD + kk] : wv[(o-H1)*DD + kk];
    }
    __syncthreads();

    for (int kt = 0; kt < DD/16; kt++) {
        const int cur = kt & 1, nxt = cur ^ 1;
        float xr_st[8], wr_st[12];
        const bool more = (kt + 1 < DD/16);
        if (more) {
            int k0 = (kt+1)*16;
            #pragma unroll
            for (int i = 0; i < 8; i++) {
                int idx = t + i*256;  int r = idx >> 4, kk = idx & 15;
                xr_st[i] = X[(size_t)(r0+r)*DD + k0 + kk];
            }
            #pragma unroll
            for (int i = 0; i < 12; i++) {
                int idx = t + i*256;  int o = idx >> 4, kk = idx & 15;
                wr_st[i] = (o < H1) ? w1[o*DD + k0 + kk] : wv[(o-H1)*DD + k0 + kk];
            }
        }
        #pragma unroll
        for (int k = 0; k < 16; k++) {
            float4 xa = *reinterpret_cast<const float4*>(&Xs[cur][k][ty*4]);
            float4 xb = *reinterpret_cast<const float4*>(&Xs[cur][k][64 + ty*4]);
            float xr[8] = {xa.x,xa.y,xa.z,xa.w, xb.x,xb.y,xb.z,xb.w};
            float4 w0 = *reinterpret_cast<const float4*>(&Ws[cur][k][tx*4]);
            float4 w1v = *reinterpret_cast<const float4*>(&Ws[cur][k][64 + tx*4]);
            float4 w2v = *reinterpret_cast<const float4*>(&Ws[cur][k][128 + tx*4]);
            float wr[12] = {w0.x,w0.y,w0.z,w0.w, w1v.x,w1v.y,w1v.z,w1v.w,
                            w2v.x,w2v.y,w2v.z,w2v.w};
            #pragma unroll
            for (int i = 0; i < 8; i++)
                #pragma unroll
                for (int j = 0; j < 12; j++)
                    acc[i][j] = fmaf(xr[i], wr[j], acc[i][j]);
        }
        if (more) {
            #pragma unroll
            for (int i = 0; i < 8; i++) {
                int idx = t + i*256;  int r = idx >> 4, kk = idx & 15;
                Xs[nxt][kk][r] = xr_st[i];
            }
            #pragma unroll
            for (int i = 0; i < 12; i++) {
                int idx = t + i*256;  int o = idx >> 4, kk = idx & 15;
                Ws[nxt][kk][o] = wr_st[i];
            }
        }
        __syncthreads();
    }
    float4 b1a = *reinterpret_cast<const float4*>(&b1[tx*4]);
    float4 b1b = *reinterpret_cast<const float4*>(&b1[64 + tx*4]);
    float ba[8] = {b1a.x,b1a.y,b1a.z,b1a.w, b1b.x,b1b.y,b1b.z,b1b.w};
    #pragma unroll
    for (int i = 0; i < 8; i++) {
        int r = r0 + (i < 4 ? ty*4 + i : 64 + ty*4 + (i-4));
        float h[8];
        #pragma unroll
        for (int j = 0; j < 8; j++) {
            float v = acc[i][j] + ba[j];
            h[j] = 0.5f * v * (1.f + erff(v * 0.7071067811865476f));
        }
        *reinterpret_cast<float4*>(&g_H[(size_t)r*H1 + tx*4])      = make_float4(h[0],h[1],h[2],h[3]);
        *reinterpret_cast<float4*>(&g_H[(size_t)r*H1 + 64 + tx*4]) = make_float4(h[4],h[5],h[6],h[7]);
        *reinterpret_cast<float4*>(&g_V[(size_t)r*DK + tx*4]) =
            make_float4(acc[i][8], acc[i][9], acc[i][10], acc[i][11]);
    }
}

// ============================================================
// K2: features = sigmoid(H@W2^T+b2); Q/K; charge0; zero g_cpack
// ============================================================
__global__ void __launch_bounds__(256) k2_feat(const float* __restrict__ w2,
        const float* __restrict__ b2, const float* __restrict__ wq,
        const float* __restrict__ wk, const float* __restrict__ wc,
        const float* __restrict__ bc) {
    __shared__ float Hs[8][H1];
    __shared__ float Fs[8][FF];
    int warp = threadIdx.x >> 5, lane = threadIdx.x & 31;
    int row = blockIdx.x * 8 + warp;

    for (int k = lane; k < H1; k += 32) Hs[warp][k] = g_H[(size_t)row*H1 + k];
    __syncwarp();
    if (lane < FF) {
        float s = b2[lane];
        #pragma unroll 4
        for (int k = 0; k < H1; k++) s = fmaf(Hs[warp][k], w2[lane*H1 + k], s);
        Fs[warp][lane] = 1.f / (1.f + __expf(-s));
    }
    __syncwarp();
    #pragma unroll
    for (int half = 0; half < 2; half++) {
        int d = lane + half*32;
        float q = 0.f, kv = 0.f;
        #pragma unroll
        for (int j = 0; j < FF; j++) {
            float fv = Fs[warp][j];
            q  = fmaf(fv, wq[d*FF + j], q);
            kv = fmaf(fv, wk[d*FF + j], kv);
        }
        g_Q[(size_t)row*DK + d] = q;
        g_K[(size_t)row*DK + d] = kv;
    }
    if (lane == 0) {
        float s = bc[0];
        #pragma unroll
        for (int j = 0; j < FF; j++) s = fmaf(Fs[warp][j], wc[j], s);
        g_ccur[row] = 1.f / (1.f + __expf(-s));
        g_cpack[row] = make_float4(0.f, 0.f, 0.f, 0.f);
    }
}

// ============================================================
// K3: compat = Q@K^T/8.  128x128 tiles (triangle), 8x8 acc.
// ============================================================
__global__ void __launch_bounds__(256) k3_compat() {
    int tc = blockIdx.x, tr = blockIdx.y, b = blockIdx.z;
    if (tc > tr) return;
    __shared__ float Qs[32][132];
    __shared__ float Ks[32][132];
    int t = threadIdx.x, tx = t & 15, ty = t >> 4;
    int r0 = tr*128, c0 = tc*128;
    const float* Qb = g_Q + (size_t)b*NN*DK;
    const float* Kb = g_K + (size_t)b*NN*DK;

    float acc[8][8];
    #pragma unroll
    for (int i = 0; i < 8; i++)
        #pragma unroll
        for (int j = 0; j < 8; j++) acc[i][j] = 0.f;

    for (int kc = 0; kc < 2; kc++) {
        int kb0 = kc*32;
        #pragma unroll
        for (int i = 0; i < 16; i++) {
            int idx = t + i*256;
            int r = idx >> 5, kk = idx & 31;
            Qs[kk][r] = Qb[(size_t)(r0+r)*DK + kb0 + kk];
            Ks[kk][r] = Kb[(size_t)(c0+r)*DK + kb0 + kk];
        }
        __syncthreads();
        #pragma unroll
        for (int k = 0; k < 32; k++) {
            float4 qa = *reinterpret_cast<const float4*>(&Qs[k][ty*4]);
            float4 qb = *reinterpret_cast<const float4*>(&Qs[k][64 + ty*4]);
            float4 ka = *reinterpret_cast<const float4*>(&Ks[k][tx*4]);
            float4 kb = *reinterpret_cast<const float4*>(&Ks[k][64 + tx*4]);
            float xr[8] = {qa.x,qa.y,qa.z,qa.w, qb.x,qb.y,qb.z,qb.w};
            float wr[8] = {ka.x,ka.y,ka.z,ka.w, kb.x,kb.y,kb.z,kb.w};
            #pragma unroll
            for (int i = 0; i < 8; i++)
                #pragma unroll
                for (int j = 0; j < 8; j++)
                    acc[i][j] = fmaf(xr[i], wr[j], acc[i][j]);
        }
        __syncthreads();
    }
    float* Cb = g_compat + (size_t)b*NN*NN;
    #pragma unroll
    for (int i = 0; i < 8; i++) {
        int n = r0 + (i < 4 ? ty*4 + i : 64 + ty*4 + (i-4));
        *reinterpret_cast<float4*>(&Cb[(size_t)n*NN + c0 + tx*4]) =
            make_float4(acc[i][0]*0.125f, acc[i][1]*0.125f, acc[i][2]*0.125f, acc[i][3]*0.125f);
        *reinterpret_cast<float4*>(&Cb[(size_t)n*NN + c0 + 64 + tx*4]) =
            make_float4(acc[i][4]*0.125f, acc[i][5]*0.125f, acc[i][6]*0.125f, acc[i][7]*0.125f);
    }
}

// ============================================================
// kA_part: partial row sums of exp(compat*(1+step*cp[n]·cp[m])).
// 512 threads: c=tid&63, g=tid>>6 (8 groups), rows r=g+8i (z[8]).
// Block (p, seg, b): row-tiles p & 31-p, col-tiles mt=seg+8k.
// ============================================================
__global__ void __launch_bounds__(512) kA_part(const float* __restrict__ step_p) {
    __shared__ float4 crp[64];
    __shared__ float sred[16][8];
    int b = blockIdx.z, seg = blockIdx.y;
    int tid = threadIdx.x, c = tid & 63, g = tid >> 6;
    int lane = tid & 31, w = tid >> 5;
    float step = *step_p;
    const float* Cb = g_compat + (size_t)b*NN*NN;
    const float4* packb = g_cpack + b*NN;

    #pragma unroll
    for (int phase = 0; phase < 2; phase++) {
        int tr = phase ? 31 - (int)blockIdx.x : (int)blockIdx.x;
        int r0 = tr*64;
        if (tid < 64) crp[tid] = packb[r0 + tid];
        __syncthreads();
        float z[8];
        #pragma unroll
        for (int i = 0; i < 8; i++) z[i] = 0.f;

        for (int mt = seg; mt <= tr; mt += NSEG) {
            int m0 = mt*64;
            float4 cc = packb[m0 + c];
            if (mt < tr) {
                #pragma unroll
                for (int i = 0; i < 8; i++) {
                    int r = g + i*8;
                    float4 cr = crp[r];
                    float dot = cr.x*cc.x + cr.y*cc.y + cr.z*cc.z + cr.w*cc.w;
                    z[i] += __expf(Cb[(size_t)(r0+r)*NN + m0 + c] * fmaf(step, dot, 1.f));
                }
            } else {            // diagonal tile: only c <= r
                #pragma unroll
                for (int i = 0; i < 8; i++) {
                    int r = g + i*8;
                    if (c <= r) {
                        float4 cr = crp[r];
                        float dot = cr.x*cc.x + cr.y*cc.y + cr.z*cc.z + cr.w*cc.w;
                        z[i] += __expf(Cb[(size_t)(r0+r)*NN + m0 + c] * fmaf(step, dot, 1.f));
                    }
                }
            }
        }
        #pragma unroll
        for (int i = 0; i < 8; i++) {
            #pragma unroll
            for (int o = 16; o; o >>= 1)
                z[i] += __shfl_xor_sync(0xffffffffu, z[i], o);
        }
        if (lane == 0) {
            #pragma unroll
            for (int i = 0; i < 8; i++) sred[w][i] = z[i];
        }
        __syncthreads();
        if (tid < 64) {
            int g2 = tid & 7, i2 = tid >> 3;      // row = g2 + 8*i2
            g_Zpart[seg][b*NN + r0 + tid] = sred[2*g2][i2] + sred[2*g2+1][i2];
        }
        __syncthreads();   // protect crp/sred before next phase
    }
}

// ============================================================
// kB_part: partial recv[m] = Σ_{n>=m} exp(l)·Zinv[n] over this
// segment's n-tiles. 512 threads: c=tid&63, g=tid>>6, rows g+8i.
// ============================================================
__global__ void __launch_bounds__(512) kB_part(const float* __restrict__ step_p) {
    __shared__ float4 cps[64];
    __shared__ float  Zs[64];
    __shared__ float  part[8][64];
    int b = blockIdx.z, seg = blockIdx.y;
    int tid = threadIdx.x, c = tid & 63, g = tid >> 6;
    float step = *step_p;
    const float* Cb = g_compat + (size_t)b*NN*NN;
    const float4* packb = g_cpack + b*NN;

    #pragma unroll
    for (int phase = 0; phase < 2; phase++) {
        int tc = phase ? 31 - (int)blockIdx.x : (int)blockIdx.x;
        int m0 = tc*64;
        int m = m0 + c;
        float4 cm = packb[m];
        float acc = 0.f;

        for (int mt = tc + seg; mt < 32; mt += NSEG) {
            int n0 = mt*64;
            if (tid < 64) {
                cps[tid] = packb[n0 + tid];
                float s = 0.f;
                #pragma unroll
                for (int q = 0; q < NSEG; q++) s += g_Zpart[q][b*NN + n0 + tid];
                Zs[tid] = 1.f / s;
            }
            __syncthreads();
            if (mt > tc) {
                #pragma unroll
                for (int i = 0; i < 8; i++) {
                    int r = g + i*8;
                    float4 cn = cps[r];
                    float dot = cm.x*cn.x + cm.y*cn.y + cm.z*cn.z + cm.w*cn.w;
                    float e = __expf(Cb[(size_t)(n0+r)*NN + m] * fmaf(step, dot, 1.f));
                    acc = fmaf(e, Zs[r], acc);
                }
            } else {            // diagonal tile: only r >= c
                #pragma unroll
                for (int i = 0; i < 8; i++) {
                    int r = g + i*8;
                    if (r >= c) {
                        float4 cn = cps[r];
                        float dot = cm.x*cn.x + cm.y*cn.y + cm.z*cn.z + cm.w*cn.w;
                        float e = __expf(Cb[(size_t)(n0+r)*NN + m] * fmaf(step, dot, 1.f));
                        acc = fmaf(e, Zs[r], acc);
                    }
                }
            }
            __syncthreads();    // protect cps/Zs before next tile
        }
        part[g][c] = acc;
        __syncthreads();
        if (tid < 64) {
            float s = 0.f;
            #pragma unroll
            for (int q = 0; q < 8; q++) s += part[q][c];
            g_Rpart[seg][b*NN + m0 + tid] = s;
        }
        __syncthreads();        // protect part before next phase
    }
}

// ============================================================
// kB2 (tiny): recv = Σ_seg Rpart; charge update; cpack comp t.
// Sole writer of ccur/cpack -> no races anywhere.
// ============================================================
__global__ void __launch_bounds__(256) kB2(int t, const float* __restrict__ decay_p) {
    int idx = blockIdx.x*256 + threadIdx.x;
    float r = 0.f;
    #pragma unroll
    for (int q = 0; q < NSEG; q++) r += g_Rpart[q][idx];
    float decay = *decay_p;
    float cprev = g_ccur[idx];
    float sig = 1.f / (1.f + __expf(-(r - 1.f)));
    float cnew = cprev * (1.f - decay*sig);
    g_ccur[idx] = cnew;
    float4 p = g_cpack[idx];
    if      (t == 0) p.x = cnew;
    else if (t == 1) p.y = cnew;
    else if (t == 2) p.z = cnew;
    else             p.w = cnew;
    g_cpack[idx] = p;
}

// ============================================================
// K5: final attention, exp recomputed in-tile, Z fused (zrun).
// Grid (32, BB) — R9-measured configuration.
// ============================================================
__global__ void __launch_bounds__(256) k5_EV(const float* __restrict__ step_p) {
    __shared__ float Es[64][68];
    __shared__ float Vs[64][68];
    __shared__ float4 crp[64];
    int b = blockIdx.y;
    int tr = blockIdx.x;
    int r0 = tr * 64;
    int t = threadIdx.x, tx = t & 15, ty = t >> 4;
    float step = *step_p;

    if (t < 64) crp[t] = g_cpack[b*NN + r0 + t];

    float acc[4][4];
    #pragma unroll
    for (int i = 0; i < 4; i++)
        #pragma unroll
        for (int j = 0; j < 4; j++) acc[i][j] = 0.f;
    float zrun[4] = {0.f, 0.f, 0.f, 0.f};

    const float* Cb = g_compat + (size_t)b*NN*NN;
    const float* Vb = g_V + (size_t)b*NN*DK;
    __syncthreads();

    const int cload = t & 63;
    for (int mt = 0; mt <= tr; mt++) {
        int m0 = mt * 64;
        bool diag = (mt == tr);
        float4 cc = g_cpack[b*NN + m0 + cload];
        #pragma unroll
        for (int i = 0; i < 16; i++) {
            int idx = t + i*256;
            int r = idx >> 6, c = idx & 63;
            float4 cr = crp[r];
            float dot = cr.x*cc.x + cr.y*cc.y + cr.z*cc.z + cr.w*cc.w;
            float e;
            if (diag && c > r) e = 0.f;
            else e = __expf(Cb[(size_t)(r0+r)*NN + m0 + c] * fmaf(step, dot, 1.f));
            Es[r][c] = e;
            Vs[r][c] = Vb[(size_t)(m0+r)*DK + c];
        }
        __syncthreads();
        #pragma unroll 4
        for (int k = 0; k < 64; k += 4) {
            float4 e0 = *reinterpret_cast<const float4*>(&Es[ty*4+0][k]);
            float4 e1 = *reinterpret_cast<const float4*>(&Es[ty*4+1][k]);
            float4 e2 = *reinterpret_cast<const float4*>(&Es[ty*4+2][k]);
            float4 e3 = *reinterpret_cast<const float4*>(&Es[ty*4+3][k]);
            float er[4][4] = {{e0.x,e0.y,e0.z,e0.w},{e1.x,e1.y,e1.z,e1.w},
                              {e2.x,e2.y,e2.z,e2.w},{e3.x,e3.y,e3.z,e3.w}};
            #pragma unroll
            for (int i = 0; i < 4; i++)
                zrun[i] += (er[i][0] + er[i][1]) + (er[i][2] + er[i][3]);
            #pragma unroll
            for (int q = 0; q < 4; q++) {
                float4 v = *reinterpret_cast<const float4*>(&Vs[k+q][tx*4]);
                float vr[4] = {v.x, v.y, v.z, v.w};
                #pragma unroll
                for (int i = 0; i < 4; i++)
                    #pragma unroll
                    for (int j = 0; j < 4; j++)
                        acc[i][j] = fmaf(er[i][q], vr[j], acc[i][j]);
            }
        }
        __syncthreads();
    }
    #pragma unroll
    for (int i = 0; i < 4; i++) {
        int row = b*NN + r0 + ty*4 + i;
        float zi = 1.f / zrun[i];
        *reinterpret_cast<float4*>(&g_AV[(size_t)row*DK + tx*4]) =
            make_float4(acc[i][0]*zi, acc[i][1]*zi, acc[i][2]*zi, acc[i][3]*zi);
    }
}

// ============================================================
// K6: out = alpha * (AV @ wo^T). 128x128 tiles, 8x8 acc.
// ============================================================
__global__ void __launch_bounds__(256) k6_out(const float* __restrict__ wo,
        const float* __restrict__ mix_p, float* __restrict__ out) {
    __shared__ float As[32][132];
    __shared__ float Ws[32][132];
    int t = threadIdx.x, tx = t & 15, ty = t >> 4;
    int r0 = blockIdx.y * 128, c0 = blockIdx.x * 128;

    float acc[8][8];
    #pragma unroll
    for (int i = 0; i < 8; i++)
        #pragma unroll
        for (int j = 0; j < 8; j++) acc[i][j] = 0.f;

    for (int kc = 0; kc < 2; kc++) {
        int kb0 = kc*32;
        #pragma unroll
        for (int i = 0; i < 16; i++) {
            int idx = t + i*256;
            int r = idx >> 5, kk = idx & 31;
            As[kk][r] = g_AV[(size_t)(r0+r)*DK + kb0 + kk];
            Ws[kk][r] = wo[(size_t)(c0+r)*DK + kb0 + kk];
        }
        __syncthreads();
        #pragma unroll
        for (int k = 0; k < 32; k++) {
            float4 aa = *reinterpret_cast<const float4*>(&As[k][ty*4]);
            float4 ab = *reinterpret_cast<const float4*>(&As[k][64 + ty*4]);
            float4 wa = *reinterpret_cast<const float4*>(&Ws[k][tx*4]);
            float4 wb = *reinterpret_cast<const float4*>(&Ws[k][64 + tx*4]);
            float xr[8] = {aa.x,aa.y,aa.z,aa.w, ab.x,ab.y,ab.z,ab.w};
            float wr[8] = {wa.x,wa.y,wa.z,wa.w, wb.x,wb.y,wb.z,wb.w};
            #pragma unroll
            for (int i = 0; i < 8; i++)
                #pragma unroll
                for (int j = 0; j < 8; j++)
                    acc[i][j] = fmaf(xr[i], wr[j], acc[i][j]);
        }
        __syncthreads();
    }
    float alpha = 0.2f / (1.f + __expf(-mix_p[0]));
    #pragma unroll
    for (int i = 0; i < 8; i++) {
        int r = r0 + (i < 4 ? ty*4 + i : 64 + ty*4 + (i-4));
        *reinterpret_cast<float4*>(&out[(size_t)r*DD + c0 + tx*4]) =
            make_float4(acc[i][0]*alpha, acc[i][1]*alpha, acc[i][2]*alpha, acc[i][3]*alpha);
        *reinterpret_cast<float4*>(&out[(size_t)r*DD + c0 + 64 + tx*4]) =
            make_float4(acc[i][4]*alpha, acc[i][5]*alpha, acc[i][6]*alpha, acc[i][7]*alpha);
    }
}

// ============================================================
extern "C" void kernel_launch(void* const* d_in, const int* in_sizes, int n_in,
                              void* d_out, int out_size) {
    const float* X       = (const float*)d_in[0];
    const float* w1      = (const float*)d_in[2];
    const float* b1      = (const float*)d_in[3];
    const float* w2      = (const float*)d_in[4];
    const float* b2      = (const float*)d_in[5];
    const float* wq      = (const float*)d_in[6];
    const float* wk      = (const float*)d_in[7];
    const float* wc      = (const float*)d_in[8];
    const float* bc      = (const float*)d_in[9];
    const float* step_p  = (const float*)d_in[10];
    const float* decay_p = (const float*)d_in[11];
    const float* wv      = (const float*)d_in[12];
    const float* wo      = (const float*)d_in[13];
    const float* mix_p   = (const float*)d_in[14];
    float* out = (float*)d_out;

    k1_gemm<<<BN/128, 256>>>(X, w1, b1, wv);
    k2_feat<<<BN/8, 256>>>(w2, b2, wq, wk, wc, bc);
    k3_compat<<<dim3(NN/128, NN/128, BB), 256>>>();
    for (int t = 0; t < NSTEPS; t++) {
        kA_part<<<dim3(16, NSEG, BB), 512>>>(step_p);
        kB_part<<<dim3(16, NSEG, BB), 512>>>(step_p);
        kB2<<<BN/256, 256>>>(t, decay_p);
    }
    k5_EV<<<dim3(NN/64, BB), 256>>>(step_p);
    k6_out<<<dim3(DD/128, BN/128), 256>>>(wo, mix_p, out);
}

// round 13
// speedup vs baseline: 1.3661x; 1.1023x over previous
#include <cuda_runtime.h>
#include <math.h>

#define BB 8
#define NN 2048
#define DD 1024
#define H1 128
#define FF 28
#define DK 64
#define NSTEPS 4
#define NSEG 8
#define NS5 4
#define BN (BB*NN)

// ---- scratch (static device globals; no runtime allocation) ----
static __device__ float  g_H[BN*H1];
static __device__ float  g_V[BN*DK];
static __device__ float  g_Q[BN*DK];
static __device__ float  g_K[BN*DK];
static __device__ float  g_compat[(size_t)BB*NN*NN];  // lower triangle valid
static __device__ float  g_ccur[BN];
static __device__ float4 g_cpack[BN];                 // (c1,c2,c3,c4)
static __device__ float  g_Zinv[BN];
static __device__ float  g_Rpart[NSEG][BN];           // partial col sums (recv)
static __device__ float  g_AV5[NS5][BN*DK];           // unnormalized AV partials
static __device__ float  g_Z5[NS5][BN];               // Z partials for k5
static __device__ float  g_AV[BN*DK];

// ============================================================
// K1: Y[16384,192] = X @ [W1|Wv]^T. 128x192 tile, 8x12 acc,
// double-buffered K-tile=16. 128 blocks.
// ============================================================
__global__ void __launch_bounds__(256) k1_gemm(const float* __restrict__ X,
        const float* __restrict__ w1, const float* __restrict__ b1,
        const float* __restrict__ wv) {
    __shared__ float Xs[2][16][132];
    __shared__ float Ws[2][16][200];
    const int t  = threadIdx.x;
    const int tx = t & 15, ty = t >> 4;
    const int r0 = blockIdx.x * 128;

    float acc[8][12];
    #pragma unroll
    for (int i = 0; i < 8; i++)
        #pragma unroll
        for (int j = 0; j < 12; j++) acc[i][j] = 0.f;

    #pragma unroll
    for (int i = 0; i < 8; i++) {
        int idx = t + i*256;  int r = idx >> 4, kk = idx & 15;
        Xs[0][kk][r] = X[(size_t)(r0+r)*DD + kk];
    }
    #pragma unroll
    for (int i = 0; i < 12; i++) {
        int idx = t + i*256;  int o = idx >> 4, kk = idx & 15;
        Ws[0][kk][o] = (o < H1) ? w1[o*DD + kk] : wv[(o-H1)*DD + kk];
    }
    __syncthreads();

    for (int kt = 0; kt < DD/16; kt++) {
        const int cur = kt & 1, nxt = cur ^ 1;
        float xr_st[8], wr_st[12];
        const bool more = (kt + 1 < DD/16);
        if (more) {
            int k0 = (kt+1)*16;
            #pragma unroll
            for (int i = 0; i < 8; i++) {
                int idx = t + i*256;  int r = idx >> 4, kk = idx & 15;
                xr_st[i] = X[(size_t)(r0+r)*DD + k0 + kk];
            }
            #pragma unroll
            for (int i = 0; i < 12; i++) {
                int idx = t + i*256;  int o = idx >> 4, kk = idx & 15;
                wr_st[i] = (o < H1) ? w1[o*DD + k0 + kk] : wv[(o-H1)*DD + k0 + kk];
            }
        }
        #pragma unroll
        for (int k = 0; k < 16; k++) {
            float4 xa = *reinterpret_cast<const float4*>(&Xs[cur][k][ty*4]);
            float4 xb = *reinterpret_cast<const float4*>(&Xs[cur][k][64 + ty*4]);
            float xr[8] = {xa.x,xa.y,xa.z,xa.w, xb.x,xb.y,xb.z,xb.w};
            float4 w0 = *reinterpret_cast<const float4*>(&Ws[cur][k][tx*4]);
            float4 w1v = *reinterpret_cast<const float4*>(&Ws[cur][k][64 + tx*4]);
            float4 w2v = *reinterpret_cast<const float4*>(&Ws[cur][k][128 + tx*4]);
            float wr[12] = {w0.x,w0.y,w0.z,w0.w, w1v.x,w1v.y,w1v.z,w1v.w,
                            w2v.x,w2v.y,w2v.z,w2v.w};
            #pragma unroll
            for (int i = 0; i < 8; i++)
                #pragma unroll
                for (int j = 0; j < 12; j++)
                    acc[i][j] = fmaf(xr[i], wr[j], acc[i][j]);
        }
        if (more) {
            #pragma unroll
            for (int i = 0; i < 8; i++) {
                int idx = t + i*256;  int r = idx >> 4, kk = idx & 15;
                Xs[nxt][kk][r] = xr_st[i];
            }
            #pragma unroll
            for (int i = 0; i < 12; i++) {
                int idx = t + i*256;  int o = idx >> 4, kk = idx & 15;
                Ws[nxt][kk][o] = wr_st[i];
            }
        }
        __syncthreads();
    }
    float4 b1a = *reinterpret_cast<const float4*>(&b1[tx*4]);
    float4 b1b = *reinterpret_cast<const float4*>(&b1[64 + tx*4]);
    float ba[8] = {b1a.x,b1a.y,b1a.z,b1a.w, b1b.x,b1b.y,b1b.z,b1b.w};
    #pragma unroll
    for (int i = 0; i < 8; i++) {
        int r = r0 + (i < 4 ? ty*4 + i : 64 + ty*4 + (i-4));
        float h[8];
        #pragma unroll
        for (int j = 0; j < 8; j++) {
            float v = acc[i][j] + ba[j];
            h[j] = 0.5f * v * (1.f + erff(v * 0.7071067811865476f));
        }
        *reinterpret_cast<float4*>(&g_H[(size_t)r*H1 + tx*4])      = make_float4(h[0],h[1],h[2],h[3]);
        *reinterpret_cast<float4*>(&g_H[(size_t)r*H1 + 64 + tx*4]) = make_float4(h[4],h[5],h[6],h[7]);
        *reinterpret_cast<float4*>(&g_V[(size_t)r*DK + tx*4]) =
            make_float4(acc[i][8], acc[i][9], acc[i][10], acc[i][11]);
    }
}

// ============================================================
// K2: features = sigmoid(H@W2^T+b2); Q/K; charge0; zero g_cpack
// ============================================================
__global__ void __launch_bounds__(256) k2_feat(const float* __restrict__ w2,
        const float* __restrict__ b2, const float* __restrict__ wq,
        const float* __restrict__ wk, const float* __restrict__ wc,
        const float* __restrict__ bc) {
    __shared__ float Hs[8][H1];
    __shared__ float Fs[8][FF];
    int warp = threadIdx.x >> 5, lane = threadIdx.x & 31;
    int row = blockIdx.x * 8 + warp;

    for (int k = lane; k < H1; k += 32) Hs[warp][k] = g_H[(size_t)row*H1 + k];
    __syncwarp();
    if (lane < FF) {
        float s = b2[lane];
        #pragma unroll 4
        for (int k = 0; k < H1; k++) s = fmaf(Hs[warp][k], w2[lane*H1 + k], s);
        Fs[warp][lane] = 1.f / (1.f + __expf(-s));
    }
    __syncwarp();
    #pragma unroll
    for (int half = 0; half < 2; half++) {
        int d = lane + half*32;
        float q = 0.f, kv = 0.f;
        #pragma unroll
        for (int j = 0; j < FF; j++) {
            float fv = Fs[warp][j];
            q  = fmaf(fv, wq[d*FF + j], q);
            kv = fmaf(fv, wk[d*FF + j], kv);
        }
        g_Q[(size_t)row*DK + d] = q;
        g_K[(size_t)row*DK + d] = kv;
    }
    if (lane == 0) {
        float s = bc[0];
        #pragma unroll
        for (int j = 0; j < FF; j++) s = fmaf(Fs[warp][j], wc[j], s);
        g_ccur[row] = 1.f / (1.f + __expf(-s));
        g_cpack[row] = make_float4(0.f, 0.f, 0.f, 0.f);
    }
}

// ============================================================
// K3: compat = Q@K^T/8.  128x128 tiles (triangle), 8x8 acc.
// ============================================================
__global__ void __launch_bounds__(256) k3_compat() {
    int tc = blockIdx.x, tr = blockIdx.y, b = blockIdx.z;
    if (tc > tr) return;
    __shared__ float Qs[32][132];
    __shared__ float Ks[32][132];
    int t = threadIdx.x, tx = t & 15, ty = t >> 4;
    int r0 = tr*128, c0 = tc*128;
    const float* Qb = g_Q + (size_t)b*NN*DK;
    const float* Kb = g_K + (size_t)b*NN*DK;

    float acc[8][8];
    #pragma unroll
    for (int i = 0; i < 8; i++)
        #pragma unroll
        for (int j = 0; j < 8; j++) acc[i][j] = 0.f;

    for (int kc = 0; kc < 2; kc++) {
        int kb0 = kc*32;
        #pragma unroll
        for (int i = 0; i < 16; i++) {
            int idx = t + i*256;
            int r = idx >> 5, kk = idx & 31;
            Qs[kk][r] = Qb[(size_t)(r0+r)*DK + kb0 + kk];
            Ks[kk][r] = Kb[(size_t)(c0+r)*DK + kb0 + kk];
        }
        __syncthreads();
        #pragma unroll
        for (int k = 0; k < 32; k++) {
            float4 qa = *reinterpret_cast<const float4*>(&Qs[k][ty*4]);
            float4 qb = *reinterpret_cast<const float4*>(&Qs[k][64 + ty*4]);
            float4 ka = *reinterpret_cast<const float4*>(&Ks[k][tx*4]);
            float4 kb = *reinterpret_cast<const float4*>(&Ks[k][64 + tx*4]);
            float xr[8] = {qa.x,qa.y,qa.z,qa.w, qb.x,qb.y,qb.z,qb.w};
            float wr[8] = {ka.x,ka.y,ka.z,ka.w, kb.x,kb.y,kb.z,kb.w};
            #pragma unroll
            for (int i = 0; i < 8; i++)
                #pragma unroll
                for (int j = 0; j < 8; j++)
                    acc[i][j] = fmaf(xr[i], wr[j], acc[i][j]);
        }
        __syncthreads();
    }
    float* Cb = g_compat + (size_t)b*NN*NN;
    #pragma unroll
    for (int i = 0; i < 8; i++) {
        int n = r0 + (i < 4 ? ty*4 + i : 64 + ty*4 + (i-4));
        *reinterpret_cast<float4*>(&Cb[(size_t)n*NN + c0 + tx*4]) =
            make_float4(acc[i][0]*0.125f, acc[i][1]*0.125f, acc[i][2]*0.125f, acc[i][3]*0.125f);
        *reinterpret_cast<float4*>(&Cb[(size_t)n*NN + c0 + 64 + tx*4]) =
            make_float4(acc[i][4]*0.125f, acc[i][5]*0.125f, acc[i][6]*0.125f, acc[i][7]*0.125f);
    }
}

// ============================================================
// kA: Zinv[n] = 1/Σ_m exp(compat*(1+step*cpack[n]·cpack[m])).
// Per-row, 4x unroll (R9-measured 38us form).
// ============================================================
__global__ void __launch_bounds__(256) kA_Z(const float* __restrict__ step_p) {
    __shared__ float red[8];
    int row = blockIdx.x;
    int b = row >> 11, n = row & (NN-1);
    float step = *step_p;
    float4 cn = g_cpack[row];
    const float* crow = g_compat + (size_t)b*NN*NN + (size_t)n*NN;
    const float4* packb = g_cpack + b*NN;

    float z = 0.f;
    int m = threadIdx.x;
    for (; m + 768 <= n; m += 1024) {
        float  c0 = crow[m],     c1 = crow[m+256], c2 = crow[m+512], c3 = crow[m+768];
        float4 p0 = packb[m],    p1 = packb[m+256], p2 = packb[m+512], p3 = packb[m+768];
        float d0 = cn.x*p0.x + cn.y*p0.y + cn.z*p0.z + cn.w*p0.w;
        float d1 = cn.x*p1.x + cn.y*p1.y + cn.z*p1.z + cn.w*p1.w;
        float d2 = cn.x*p2.x + cn.y*p2.y + cn.z*p2.z + cn.w*p2.w;
        float d3 = cn.x*p3.x + cn.y*p3.y + cn.z*p3.z + cn.w*p3.w;
        float e0 = __expf(c0 * fmaf(step, d0, 1.f));
        float e1 = __expf(c1 * fmaf(step, d1, 1.f));
        float e2 = __expf(c2 * fmaf(step, d2, 1.f));
        float e3 = __expf(c3 * fmaf(step, d3, 1.f));
        z += (e0 + e1) + (e2 + e3);
    }
    for (; m <= n; m += 256) {
        float4 cm = packb[m];
        float dot = cn.x*cm.x + cn.y*cm.y + cn.z*cm.z + cn.w*cm.w;
        z += __expf(crow[m] * fmaf(step, dot, 1.f));
    }
    int lane = threadIdx.x & 31, w = threadIdx.x >> 5;
    #pragma unroll
    for (int o = 16; o; o >>= 1) z += __shfl_xor_sync(0xffffffffu, z, o);
    if (lane == 0) red[w] = z;
    __syncthreads();
    if (threadIdx.x == 0) {
        float zt = red[0];
        #pragma unroll
        for (int i = 1; i < 8; i++) zt += red[i];
        g_Zinv[row] = 1.f / zt;
    }
}

// ============================================================
// kB_part: partial recv[m] = Σ exp(l)·Zinv[n] over this seg's
// n-tiles. SYNC-FREE mainloop: cpack[n]/Zinv[n] read directly
// from gmem (warp-uniform -> L1 broadcast). 512 threads.
// ============================================================
__global__ void __launch_bounds__(512) kB_part(const float* __restrict__ step_p) {
    __shared__ float part[8][64];
    int b = blockIdx.z, seg = blockIdx.y;
    int tid = threadIdx.x, c = tid & 63, g = tid >> 6;
    float step = *step_p;
    const float* Cb = g_compat + (size_t)b*NN*NN;
    const float* Zb = g_Zinv + b*NN;
    const float4* packb = g_cpack + b*NN;

    #pragma unroll
    for (int phase = 0; phase < 2; phase++) {
        int tc = phase ? 31 - (int)blockIdx.x : (int)blockIdx.x;
        int m0 = tc*64;
        int m = m0 + c;
        float4 cm = packb[m];
        float acc = 0.f;

        for (int mt = tc + seg; mt < 32; mt += NSEG) {
            int n0 = mt*64;
            bool diag = (mt == tc);
            #pragma unroll
            for (int i = 0; i < 8; i++) {
                int r = g + i*8;
                if (!diag || r >= c) {
                    float4 cn = packb[n0 + r];           // warp-uniform
                    float zi = Zb[n0 + r];               // warp-uniform
                    float dot = cm.x*cn.x + cm.y*cn.y + cm.z*cn.z + cm.w*cn.w;
                    float e = __expf(Cb[(size_t)(n0+r)*NN + m] * fmaf(step, dot, 1.f));
                    acc = fmaf(e, zi, acc);
                }
            }
        }
        part[g][c] = acc;
        __syncthreads();
        if (tid < 64) {
            float s = 0.f;
            #pragma unroll
            for (int q = 0; q < 8; q++) s += part[q][c];
            g_Rpart[seg][b*NN + m0 + tid] = s;
        }
        __syncthreads();        // protect part before next phase
    }
}

// ============================================================
// kB2 (tiny): recv = Σ_seg Rpart; charge update; cpack comp t.
// ============================================================
__global__ void __launch_bounds__(256) kB2(int t, const float* __restrict__ decay_p) {
    int idx = blockIdx.x*256 + threadIdx.x;
    float r = 0.f;
    #pragma unroll
    for (int q = 0; q < NSEG; q++) r += g_Rpart[q][idx];
    float decay = *decay_p;
    float cprev = g_ccur[idx];
    float sig = 1.f / (1.f + __expf(-(r - 1.f)));
    float cnew = cprev * (1.f - decay*sig);
    g_ccur[idx] = cnew;
    float4 p = g_cpack[idx];
    if      (t == 0) p.x = cnew;
    else if (t == 1) p.y = cnew;
    else if (t == 2) p.z = cnew;
    else             p.w = cnew;
    g_cpack[idx] = p;
}

// ============================================================
// k5_part: segmented final attention. Block (p, seg, b):
// row-tiles p & 31-p (pairing), col-tiles mt ≡ seg (mod NS5).
// Writes unnormalized AV partials + Z partials.
// ============================================================
__global__ void __launch_bounds__(256) k5_part(const float* __restrict__ step_p) {
    __shared__ float Es[64][68];
    __shared__ float Vs[64][68];
    __shared__ float4 crp[64];
    int b = blockIdx.z, seg = blockIdx.y;
    int t = threadIdx.x, tx = t & 15, ty = t >> 4;
    float step = *step_p;
    const float* Cb = g_compat + (size_t)b*NN*NN;
    const float* Vb = g_V + (size_t)b*NN*DK;
    const int cload = t & 63;

    #pragma unroll
    for (int phase = 0; phase < 2; phase++) {
        int tr = phase ? 31 - (int)blockIdx.x : (int)blockIdx.x;
        int r0 = tr * 64;
        if (t < 64) crp[t] = g_cpack[b*NN + r0 + t];
        __syncthreads();

        float acc[4][4];
        #pragma unroll
        for (int i = 0; i < 4; i++)
            #pragma unroll
            for (int j = 0; j < 4; j++) acc[i][j] = 0.f;
        float zrun[4] = {0.f, 0.f, 0.f, 0.f};

        for (int mt = seg; mt <= tr; mt += NS5) {
            int m0 = mt * 64;
            bool diag = (mt == tr);
            float4 cc = g_cpack[b*NN + m0 + cload];
            #pragma unroll
            for (int i = 0; i < 16; i++) {
                int idx = t + i*256;
                int r = idx >> 6, c = idx & 63;
                float4 cr = crp[r];
                float dot = cr.x*cc.x + cr.y*cc.y + cr.z*cc.z + cr.w*cc.w;
                float e;
                if (diag && c > r) e = 0.f;
                else e = __expf(Cb[(size_t)(r0+r)*NN + m0 + c] * fmaf(step, dot, 1.f));
                Es[r][c] = e;
                Vs[r][c] = Vb[(size_t)(m0+r)*DK + c];
            }
            __syncthreads();
            #pragma unroll 4
            for (int k = 0; k < 64; k += 4) {
                float4 e0 = *reinterpret_cast<const float4*>(&Es[ty*4+0][k]);
                float4 e1 = *reinterpret_cast<const float4*>(&Es[ty*4+1][k]);
                float4 e2 = *reinterpret_cast<const float4*>(&Es[ty*4+2][k]);
                float4 e3 = *reinterpret_cast<const float4*>(&Es[ty*4+3][k]);
                float er[4][4] = {{e0.x,e0.y,e0.z,e0.w},{e1.x,e1.y,e1.z,e1.w},
                                  {e2.x,e2.y,e2.z,e2.w},{e3.x,e3.y,e3.z,e3.w}};
                #pragma unroll
                for (int i = 0; i < 4; i++)
                    zrun[i] += (er[i][0] + er[i][1]) + (er[i][2] + er[i][3]);
                #pragma unroll
                for (int q = 0; q < 4; q++) {
                    float4 v = *reinterpret_cast<const float4*>(&Vs[k+q][tx*4]);
                    float vr[4] = {v.x, v.y, v.z, v.w};
                    #pragma unroll
                    for (int i = 0; i < 4; i++)
                        #pragma unroll
                        for (int j = 0; j < 4; j++)
                            acc[i][j] = fmaf(er[i][q], vr[j], acc[i][j]);
                }
            }
            __syncthreads();
        }
        #pragma unroll
        for (int i = 0; i < 4; i++) {
            int row = b*NN + r0 + ty*4 + i;
            *reinterpret_cast<float4*>(&g_AV5[seg][(size_t)row*DK + tx*4]) =
                make_float4(acc[i][0], acc[i][1], acc[i][2], acc[i][3]);
            if (tx == 0) g_Z5[seg][row] = zrun[i];
        }
        __syncthreads();        // protect crp before next phase
    }
}

// ============================================================
// k5red: AV = (Σ_seg AV5) / (Σ_seg Z5). One float4 per thread.
// ============================================================
__global__ void __launch_bounds__(256) k5red() {
    int idx4 = blockIdx.x*256 + threadIdx.x;      // 0 .. BN*DK/4-1
    int row = idx4 >> 4;                           // DK/4 = 16 float4 per row
    float z = 0.f;
    #pragma unroll
    for (int q = 0; q < NS5; q++) z += g_Z5[q][row];
    float zi = 1.f / z;
    float4 a = make_float4(0.f, 0.f, 0.f, 0.f);
    #pragma unroll
    for (int q = 0; q < NS5; q++) {
        float4 p = *reinterpret_cast<const float4*>(&g_AV5[q][(size_t)idx4*4]);
        a.x += p.x; a.y += p.y; a.z += p.z; a.w += p.w;
    }
    *reinterpret_cast<float4*>(&g_AV[(size_t)idx4*4]) =
        make_float4(a.x*zi, a.y*zi, a.z*zi, a.w*zi);
}

// ============================================================
// K6: out = alpha * (AV @ wo^T). 128x128 tiles, 8x8 acc.
// ============================================================
__global__ void __launch_bounds__(256) k6_out(const float* __restrict__ wo,
        const float* __restrict__ mix_p, float* __restrict__ out) {
    __shared__ float As[32][132];
    __shared__ float Ws[32][132];
    int t = threadIdx.x, tx = t & 15, ty = t >> 4;
    int r0 = blockIdx.y * 128, c0 = blockIdx.x * 128;

    float acc[8][8];
    #pragma unroll
    for (int i = 0; i < 8; i++)
        #pragma unroll
        for (int j = 0; j < 8; j++) acc[i][j] = 0.f;

    for (int kc = 0; kc < 2; kc++) {
        int kb0 = kc*32;
        #pragma unroll
        for (int i = 0; i < 16; i++) {
            int idx = t + i*256;
            int r = idx >> 5, kk = idx & 31;
            As[kk][r] = g_AV[(size_t)(r0+r)*DK + kb0 + kk];
            Ws[kk][r] = wo[(size_t)(c0+r)*DK + kb0 + kk];
        }
        __syncthreads();
        #pragma unroll
        for (int k = 0; k < 32; k++) {
            float4 aa = *reinterpret_cast<const float4*>(&As[k][ty*4]);
            float4 ab = *reinterpret_cast<const float4*>(&As[k][64 + ty*4]);
            float4 wa = *reinterpret_cast<const float4*>(&Ws[k][tx*4]);
            float4 wb = *reinterpret_cast<const float4*>(&Ws[k][64 + tx*4]);
            float xr[8] = {aa.x,aa.y,aa.z,aa.w, ab.x,ab.y,ab.z,ab.w};
            float wr[8] = {wa.x,wa.y,wa.z,wa.w, wb.x,wb.y,wb.z,wb.w};
            #pragma unroll
            for (int i = 0; i < 8; i++)
                #pragma unroll
                for (int j = 0; j < 8; j++)
                    acc[i][j] = fmaf(xr[i], wr[j], acc[i][j]);
        }
        __syncthreads();
    }
    float alpha = 0.2f / (1.f + __expf(-mix_p[0]));
    #pragma unroll
    for (int i = 0; i < 8; i++) {
        int r = r0 + (i < 4 ? ty*4 + i : 64 + ty*4 + (i-4));
        *reinterpret_cast<float4*>(&out[(size_t)r*DD + c0 + tx*4]) =
            make_float4(acc[i][0]*alpha, acc[i][1]*alpha, acc[i][2]*alpha, acc[i][3]*alpha);
        *reinterpret_cast<float4*>(&out[(size_t)r*DD + c0 + 64 + tx*4]) =
            make_float4(acc[i][4]*alpha, acc[i][5]*alpha, acc[i][6]*alpha, acc[i][7]*alpha);
    }
}

// ============================================================
extern "C" void kernel_launch(void* const* d_in, const int* in_sizes, int n_in,
                              void* d_out, int out_size) {
    const float* X       = (const float*)d_in[0];
    const float* w1      = (const float*)d_in[2];
    const float* b1      = (const float*)d_in[3];
    const float* w2      = (const float*)d_in[4];
    const float* b2      = (const float*)d_in[5];
    const float* wq      = (const float*)d_in[6];
    const float* wk      = (const float*)d_in[7];
    const float* wc      = (const float*)d_in[8];
    const float* bc      = (const float*)d_in[9];
    const float* step_p  = (const float*)d_in[10];
    const float* decay_p = (const float*)d_in[11];
    const float* wv      = (const float*)d_in[12];
    const float* wo      = (const float*)d_in[13];
    const float* mix_p   = (const float*)d_in[14];
    float* out = (float*)d_out;

    k1_gemm<<<BN/128, 256>>>(X, w1, b1, wv);
    k2_feat<<<BN/8, 256>>>(w2, b2, wq, wk, wc, bc);
    k3_compat<<<dim3(NN/128, NN/128, BB), 256>>>();
    for (int t = 0; t < NSTEPS; t++) {
        kA_Z<<<BN, 256>>>(step_p);
        kB_part<<<dim3(16, NSEG, BB), 512>>>(step_p);
        kB2<<<BN/256, 256>>>(t, decay_p);
    }
    k5_part<<<dim3(16, NS5, BB), 256>>>(step_p);
    k5red<<<BN*DK/1024, 256>>>();
    k6_out<<<dim3(DD/128, BN/128), 256>>>(wo, mix_p, out);
}

// round 15
// speedup vs baseline: 1.3827x; 1.0121x over previous
#include <cuda_runtime.h>
#include <math.h>

#define BB 8
#define NN 2048
#define DD 1024
#define H1 128
#define FF 28
#define DK 64
#define NSTEPS 4
#define NSEG 8
#define NS5 4
#define BN (BB*NN)

// ---- scratch (static device globals; no runtime allocation) ----
static __device__ float  g_H[BN*H1];
static __device__ float  g_V[BN*DK];
static __device__ float  g_Q[BN*DK];
static __device__ float  g_K[BN*DK];
static __device__ float  g_compat[(size_t)BB*NN*NN];  // lower triangle valid
static __device__ float  g_ccur[BN];
static __device__ float4 g_cpack[BN];                 // (c1,c2,c3,c4)
static __device__ float  g_Zinv[BN];
static __device__ float  g_Rpart[NSEG][BN];           // partial col sums (recv)
static __device__ float  g_AV5[NS5][BN*DK];           // unnormalized AV partials
static __device__ float  g_Z5[NS5][BN];               // Z partials for k5
static __device__ float  g_AV[BN*DK];

// ============================================================
// K1: Y[16384,192] = X @ [W1|Wv]^T. 128x192 tile, 8x12 acc,
// double-buffered K-tile=16. 128 blocks.
// ============================================================
__global__ void __launch_bounds__(256) k1_gemm(const float* __restrict__ X,
        const float* __restrict__ w1, const float* __restrict__ b1,
        const float* __restrict__ wv) {
    __shared__ float Xs[2][16][132];
    __shared__ float Ws[2][16][200];
    const int t  = threadIdx.x;
    const int tx = t & 15, ty = t >> 4;
    const int r0 = blockIdx.x * 128;

    float acc[8][12];
    #pragma unroll
    for (int i = 0; i < 8; i++)
        #pragma unroll
        for (int j = 0; j < 12; j++) acc[i][j] = 0.f;

    #pragma unroll
    for (int i = 0; i < 8; i++) {
        int idx = t + i*256;  int r = idx >> 4, kk = idx & 15;
        Xs[0][kk][r] = X[(size_t)(r0+r)*DD + kk];
    }
    #pragma unroll
    for (int i = 0; i < 12; i++) {
        int idx = t + i*256;  int o = idx >> 4, kk = idx & 15;
        Ws[0][kk][o] = (o < H1) ? w1[o*DD + kk] : wv[(o-H1)*DD + kk];
    }
    __syncthreads();

    for (int kt = 0; kt < DD/16; kt++) {
        const int cur = kt & 1, nxt = cur ^ 1;
        float xr_st[8], wr_st[12];
        const bool more = (kt + 1 < DD/16);
        if (more) {
            int k0 = (kt+1)*16;
            #pragma unroll
            for (int i = 0; i < 8; i++) {
                int idx = t + i*256;  int r = idx >> 4, kk = idx & 15;
                xr_st[i] = X[(size_t)(r0+r)*DD + k0 + kk];
            }
            #pragma unroll
            for (int i = 0; i < 12; i++) {
                int idx = t + i*256;  int o = idx >> 4, kk = idx & 15;
                wr_st[i] = (o < H1) ? w1[o*DD + k0 + kk] : wv[(o-H1)*DD + k0 + kk];
            }
        }
        #pragma unroll
        for (int k = 0; k < 16; k++) {
            float4 xa = *reinterpret_cast<const float4*>(&Xs[cur][k][ty*4]);
            float4 xb = *reinterpret_cast<const float4*>(&Xs[cur][k][64 + ty*4]);
            float xr[8] = {xa.x,xa.y,xa.z,xa.w, xb.x,xb.y,xb.z,xb.w};
            float4 w0 = *reinterpret_cast<const float4*>(&Ws[cur][k][tx*4]);
            float4 w1v = *reinterpret_cast<const float4*>(&Ws[cur][k][64 + tx*4]);
            float4 w2v = *reinterpret_cast<const float4*>(&Ws[cur][k][128 + tx*4]);
            float wr[12] = {w0.x,w0.y,w0.z,w0.w, w1v.x,w1v.y,w1v.z,w1v.w,
                            w2v.x,w2v.y,w2v.z,w2v.w};
            #pragma unroll
            for (int i = 0; i < 8; i++)
                #pragma unroll
                for (int j = 0; j < 12; j++)
                    acc[i][j] = fmaf(xr[i], wr[j], acc[i][j]);
        }
        if (more) {
            #pragma unroll
            for (int i = 0; i < 8; i++) {
                int idx = t + i*256;  int r = idx >> 4, kk = idx & 15;
                Xs[nxt][kk][r] = xr_st[i];
            }
            #pragma unroll
            for (int i = 0; i < 12; i++) {
                int idx = t + i*256;  int o = idx >> 4, kk = idx & 15;
                Ws[nxt][kk][o] = wr_st[i];
            }
        }
        __syncthreads();
    }
    float4 b1a = *reinterpret_cast<const float4*>(&b1[tx*4]);
    float4 b1b = *reinterpret_cast<const float4*>(&b1[64 + tx*4]);
    float ba[8] = {b1a.x,b1a.y,b1a.z,b1a.w, b1b.x,b1b.y,b1b.z,b1b.w};
    #pragma unroll
    for (int i = 0; i < 8; i++) {
        int r = r0 + (i < 4 ? ty*4 + i : 64 + ty*4 + (i-4));
        float h[8];
        #pragma unroll
        for (int j = 0; j < 8; j++) {
            float v = acc[i][j] + ba[j];
            h[j] = 0.5f * v * (1.f + erff(v * 0.7071067811865476f));
        }
        *reinterpret_cast<float4*>(&g_H[(size_t)r*H1 + tx*4])      = make_float4(h[0],h[1],h[2],h[3]);
        *reinterpret_cast<float4*>(&g_H[(size_t)r*H1 + 64 + tx*4]) = make_float4(h[4],h[5],h[6],h[7]);
        *reinterpret_cast<float4*>(&g_V[(size_t)r*DK + tx*4]) =
            make_float4(acc[i][8], acc[i][9], acc[i][10], acc[i][11]);
    }
}

// ============================================================
// K2: features = sigmoid(H@W2^T+b2); Q/K; charge0; zero g_cpack
// ============================================================
__global__ void __launch_bounds__(256) k2_feat(const float* __restrict__ w2,
        const float* __restrict__ b2, const float* __restrict__ wq,
        const float* __restrict__ wk, const float* __restrict__ wc,
        const float* __restrict__ bc) {
    __shared__ float Hs[8][H1];
    __shared__ float Fs[8][FF];
    int warp = threadIdx.x >> 5, lane = threadIdx.x & 31;
    int row = blockIdx.x * 8 + warp;

    for (int k = lane; k < H1; k += 32) Hs[warp][k] = g_H[(size_t)row*H1 + k];
    __syncwarp();
    if (lane < FF) {
        float s = b2[lane];
        #pragma unroll 4
        for (int k = 0; k < H1; k++) s = fmaf(Hs[warp][k], w2[lane*H1 + k], s);
        Fs[warp][lane] = 1.f / (1.f + __expf(-s));
    }
    __syncwarp();
    #pragma unroll
    for (int half = 0; half < 2; half++) {
        int d = lane + half*32;
        float q = 0.f, kv = 0.f;
        #pragma unroll
        for (int j = 0; j < FF; j++) {
            float fv = Fs[warp][j];
            q  = fmaf(fv, wq[d*FF + j], q);
            kv = fmaf(fv, wk[d*FF + j], kv);
        }
        g_Q[(size_t)row*DK + d] = q;
        g_K[(size_t)row*DK + d] = kv;
    }
    if (lane == 0) {
        float s = bc[0];
        #pragma unroll
        for (int j = 0; j < FF; j++) s = fmaf(Fs[warp][j], wc[j], s);
        g_ccur[row] = 1.f / (1.f + __expf(-s));
        g_cpack[row] = make_float4(0.f, 0.f, 0.f, 0.f);
    }
}

// ============================================================
// K3: compat = Q@K^T/8.  128x128 tiles (triangle), 8x8 acc.
// ============================================================
__global__ void __launch_bounds__(256) k3_compat() {
    int tc = blockIdx.x, tr = blockIdx.y, b = blockIdx.z;
    if (tc > tr) return;
    __shared__ float Qs[32][132];
    __shared__ float Ks[32][132];
    int t = threadIdx.x, tx = t & 15, ty = t >> 4;
    int r0 = tr*128, c0 = tc*128;
    const float* Qb = g_Q + (size_t)b*NN*DK;
    const float* Kb = g_K + (size_t)b*NN*DK;

    float acc[8][8];
    #pragma unroll
    for (int i = 0; i < 8; i++)
        #pragma unroll
        for (int j = 0; j < 8; j++) acc[i][j] = 0.f;

    for (int kc = 0; kc < 2; kc++) {
        int kb0 = kc*32;
        #pragma unroll
        for (int i = 0; i < 16; i++) {
            int idx = t + i*256;
            int r = idx >> 5, kk = idx & 31;
            Qs[kk][r] = Qb[(size_t)(r0+r)*DK + kb0 + kk];
            Ks[kk][r] = Kb[(size_t)(c0+r)*DK + kb0 + kk];
        }
        __syncthreads();
        #pragma unroll
        for (int k = 0; k < 32; k++) {
            float4 qa = *reinterpret_cast<const float4*>(&Qs[k][ty*4]);
            float4 qb = *reinterpret_cast<const float4*>(&Qs[k][64 + ty*4]);
            float4 ka = *reinterpret_cast<const float4*>(&Ks[k][tx*4]);
            float4 kb = *reinterpret_cast<const float4*>(&Ks[k][64 + tx*4]);
            float xr[8] = {qa.x,qa.y,qa.z,qa.w, qb.x,qb.y,qb.z,qb.w};
            float wr[8] = {ka.x,ka.y,ka.z,ka.w, kb.x,kb.y,kb.z,kb.w};
            #pragma unroll
            for (int i = 0; i < 8; i++)
                #pragma unroll
                for (int j = 0; j < 8; j++)
                    acc[i][j] = fmaf(xr[i], wr[j], acc[i][j]);
        }
        __syncthreads();
    }
    float* Cb = g_compat + (size_t)b*NN*NN;
    #pragma unroll
    for (int i = 0; i < 8; i++) {
        int n = r0 + (i < 4 ? ty*4 + i : 64 + ty*4 + (i-4));
        *reinterpret_cast<float4*>(&Cb[(size_t)n*NN + c0 + tx*4]) =
            make_float4(acc[i][0]*0.125f, acc[i][1]*0.125f, acc[i][2]*0.125f, acc[i][3]*0.125f);
        *reinterpret_cast<float4*>(&Cb[(size_t)n*NN + c0 + 64 + tx*4]) =
            make_float4(acc[i][4]*0.125f, acc[i][5]*0.125f, acc[i][6]*0.125f, acc[i][7]*0.125f);
    }
}

// ============================================================
// kA_warp: Zinv via warp-per-row streaming. Each warp owns a
// complement row pair (p, 2047-p) -> exactly 2049 elements.
// No smem, no __syncthreads; shuffle reduction only.
// Grid 1024 blocks x 8 warps = 8192 pairs = all rows.
// ============================================================
__global__ void __launch_bounds__(256) kA_warp(const float* __restrict__ step_p) {
    int w = threadIdx.x >> 5, lane = threadIdx.x & 31;
    int pair = blockIdx.x * 8 + w;          // 0..8191
    int b = pair >> 10;                      // pair / 1024
    int p = pair & 1023;
    float step = *step_p;
    const float* Cb = g_compat + (size_t)b*NN*NN;
    const float4* packb = g_cpack + b*NN;

    #pragma unroll
    for (int rr = 0; rr < 2; rr++) {
        int n = rr ? (NN - 1 - p) : p;
        float4 cn = packb[n];
        const float* crow = Cb + (size_t)n*NN;
        float z = 0.f;
        int m = lane;
        for (; m + 96 <= n; m += 128) {
            float  c0 = crow[m],    c1 = crow[m+32],  c2 = crow[m+64],  c3 = crow[m+96];
            float4 p0 = packb[m],   p1 = packb[m+32], p2 = packb[m+64], p3 = packb[m+96];
            float d0 = cn.x*p0.x + cn.y*p0.y + cn.z*p0.z + cn.w*p0.w;
            float d1 = cn.x*p1.x + cn.y*p1.y + cn.z*p1.z + cn.w*p1.w;
            float d2 = cn.x*p2.x + cn.y*p2.y + cn.z*p2.z + cn.w*p2.w;
            float d3 = cn.x*p3.x + cn.y*p3.y + cn.z*p3.z + cn.w*p3.w;
            float e0 = __expf(c0 * fmaf(step, d0, 1.f));
            float e1 = __expf(c1 * fmaf(step, d1, 1.f));
            float e2 = __expf(c2 * fmaf(step, d2, 1.f));
            float e3 = __expf(c3 * fmaf(step, d3, 1.f));
            z += (e0 + e1) + (e2 + e3);
        }
        for (; m <= n; m += 32) {
            float4 cm = packb[m];
            float dot = cn.x*cm.x + cn.y*cm.y + cn.z*cm.z + cn.w*cm.w;
            z += __expf(crow[m] * fmaf(step, dot, 1.f));
        }
        #pragma unroll
        for (int o = 16; o; o >>= 1) z += __shfl_xor_sync(0xffffffffu, z, o);
        if (lane == 0) g_Zinv[b*NN + n] = 1.f / z;
    }
}

// ============================================================
// kB_part: partial recv[m] = Σ exp(l)·Zinv[n] over this seg's
// n-tiles. SYNC-FREE mainloop: cpack[n]/Zinv[n] read directly
// from gmem (warp-uniform -> L1 broadcast). 512 threads.
// ============================================================
__global__ void __launch_bounds__(512) kB_part(const float* __restrict__ step_p) {
    __shared__ float part[8][64];
    int b = blockIdx.z, seg = blockIdx.y;
    int tid = threadIdx.x, c = tid & 63, g = tid >> 6;
    float step = *step_p;
    const float* Cb = g_compat + (size_t)b*NN*NN;
    const float* Zb = g_Zinv + b*NN;
    const float4* packb = g_cpack + b*NN;

    #pragma unroll
    for (int phase = 0; phase < 2; phase++) {
        int tc = phase ? 31 - (int)blockIdx.x : (int)blockIdx.x;
        int m0 = tc*64;
        int m = m0 + c;
        float4 cm = packb[m];
        float acc = 0.f;

        for (int mt = tc + seg; mt < 32; mt += NSEG) {
            int n0 = mt*64;
            bool diag = (mt == tc);
            #pragma unroll
            for (int i = 0; i < 8; i++) {
                int r = g + i*8;
                if (!diag || r >= c) {
                    float4 cn = packb[n0 + r];           // warp-uniform
                    float zi = Zb[n0 + r];               // warp-uniform
                    float dot = cm.x*cn.x + cm.y*cn.y + cm.z*cn.z + cm.w*cn.w;
                    float e = __expf(Cb[(size_t)(n0+r)*NN + m] * fmaf(step, dot, 1.f));
                    acc = fmaf(e, zi, acc);
                }
            }
        }
        part[g][c] = acc;
        __syncthreads();
        if (tid < 64) {
            float s = 0.f;
            #pragma unroll
            for (int q = 0; q < 8; q++) s += part[q][c];
            g_Rpart[seg][b*NN + m0 + tid] = s;
        }
        __syncthreads();        // protect part before next phase
    }
}

// ============================================================
// kB2 (tiny): recv = Σ_seg Rpart; charge update; cpack comp t.
// ============================================================
__global__ void __launch_bounds__(256) kB2(int t, const float* __restrict__ decay_p) {
    int idx = blockIdx.x*256 + threadIdx.x;
    float r = 0.f;
    #pragma unroll
    for (int q = 0; q < NSEG; q++) r += g_Rpart[q][idx];
    float decay = *decay_p;
    float cprev = g_ccur[idx];
    float sig = 1.f / (1.f + __expf(-(r - 1.f)));
    float cnew = cprev * (1.f - decay*sig);
    g_ccur[idx] = cnew;
    float4 p = g_cpack[idx];
    if      (t == 0) p.x = cnew;
    else if (t == 1) p.y = cnew;
    else if (t == 2) p.z = cnew;
    else             p.w = cnew;
    g_cpack[idx] = p;
}

// ============================================================
// k5_part: segmented final attention. Block (p, seg, b):
// row-tiles p & 31-p (pairing), col-tiles mt ≡ seg (mod NS5).
// Writes unnormalized AV partials + Z partials.
// ============================================================
__global__ void __launch_bounds__(256) k5_part(const float* __restrict__ step_p) {
    __shared__ float Es[64][68];
    __shared__ float Vs[64][68];
    __shared__ float4 crp[64];
    int b = blockIdx.z, seg = blockIdx.y;
    int t = threadIdx.x, tx = t & 15, ty = t >> 4;
    float step = *step_p;
    const float* Cb = g_compat + (size_t)b*NN*NN;
    const float* Vb = g_V + (size_t)b*NN*DK;
    const int cload = t & 63;

    #pragma unroll
    for (int phase = 0; phase < 2; phase++) {
        int tr = phase ? 31 - (int)blockIdx.x : (int)blockIdx.x;
        int r0 = tr * 64;
        if (t < 64) crp[t] = g_cpack[b*NN + r0 + t];
        __syncthreads();

        float acc[4][4];
        #pragma unroll
        for (int i = 0; i < 4; i++)
            #pragma unroll
            for (int j = 0; j < 4; j++) acc[i][j] = 0.f;
        float zrun[4] = {0.f, 0.f, 0.f, 0.f};

        for (int mt = seg; mt <= tr; mt += NS5) {
            int m0 = mt * 64;
            bool diag = (mt == tr);
            float4 cc = g_cpack[b*NN + m0 + cload];
            #pragma unroll
            for (int i = 0; i < 16; i++) {
                int idx = t + i*256;
                int r = idx >> 6, c = idx & 63;
                float4 cr = crp[r];
                float dot = cr.x*cc.x + cr.y*cc.y + cr.z*cc.z + cr.w*cc.w;
                float e;
                if (diag && c > r) e = 0.f;
                else e = __expf(Cb[(size_t)(r0+r)*NN + m0 + c] * fmaf(step, dot, 1.f));
                Es[r][c] = e;
                Vs[r][c] = Vb[(size_t)(m0+r)*DK + c];
            }
            __syncthreads();
            #pragma unroll 4
            for (int k = 0; k < 64; k += 4) {
                float4 e0 = *reinterpret_cast<const float4*>(&Es[ty*4+0][k]);
                float4 e1 = *reinterpret_cast<const float4*>(&Es[ty*4+1][k]);
                float4 e2 = *reinterpret_cast<const float4*>(&Es[ty*4+2][k]);
                float4 e3 = *reinterpret_cast<const float4*>(&Es[ty*4+3][k]);
                float er[4][4] = {{e0.x,e0.y,e0.z,e0.w},{e1.x,e1.y,e1.z,e1.w},
                                  {e2.x,e2.y,e2.z,e2.w},{e3.x,e3.y,e3.z,e3.w}};
                #pragma unroll
                for (int i = 0; i < 4; i++)
                    zrun[i] += (er[i][0] + er[i][1]) + (er[i][2] + er[i][3]);
                #pragma unroll
                for (int q = 0; q < 4; q++) {
                    float4 v = *reinterpret_cast<const float4*>(&Vs[k+q][tx*4]);
                    float vr[4] = {v.x, v.y, v.z, v.w};
                    #pragma unroll
                    for (int i = 0; i < 4; i++)
                        #pragma unroll
                        for (int j = 0; j < 4; j++)
                            acc[i][j] = fmaf(er[i][q], vr[j], acc[i][j]);
                }
            }
            __syncthreads();
        }
        #pragma unroll
        for (int i = 0; i < 4; i++) {
            int row = b*NN + r0 + ty*4 + i;
            *reinterpret_cast<float4*>(&g_AV5[seg][(size_t)row*DK + tx*4]) =
                make_float4(acc[i][0], acc[i][1], acc[i][2], acc[i][3]);
            if (tx == 0) g_Z5[seg][row] = zrun[i];
        }
        __syncthreads();        // protect crp before next phase
    }
}

// ============================================================
// k5red: AV = (Σ_seg AV5) / (Σ_seg Z5). One float4 per thread.
// ============================================================
__global__ void __launch_bounds__(256) k5red() {
    int idx4 = blockIdx.x*256 + threadIdx.x;      // 0 .. BN*DK/4-1
    int row = idx4 >> 4;                           // DK/4 = 16 float4 per row
    float z = 0.f;
    #pragma unroll
    for (int q = 0; q < NS5; q++) z += g_Z5[q][row];
    float zi = 1.f / z;
    float4 a = make_float4(0.f, 0.f, 0.f, 0.f);
    #pragma unroll
    for (int q = 0; q < NS5; q++) {
        float4 p = *reinterpret_cast<const float4*>(&g_AV5[q][(size_t)idx4*4]);
        a.x += p.x; a.y += p.y; a.z += p.z; a.w += p.w;
    }
    *reinterpret_cast<float4*>(&g_AV[(size_t)idx4*4]) =
        make_float4(a.x*zi, a.y*zi, a.z*zi, a.w*zi);
}

// ============================================================
// K6: out = alpha * (AV @ wo^T). 128x128 tiles, 8x8 acc.
// ============================================================
__global__ void __launch_bounds__(256) k6_out(const float* __restrict__ wo,
        const float* __restrict__ mix_p, float* __restrict__ out) {
    __shared__ float As[32][132];
    __shared__ float Ws[32][132];
    int t = threadIdx.x, tx = t & 15, ty = t >> 4;
    int r0 = blockIdx.y * 128, c0 = blockIdx.x * 128;

    float acc[8][8];
    #pragma unroll
    for (int i = 0; i < 8; i++)
        #pragma unroll
        for (int j = 0; j < 8; j++) acc[i][j] = 0.f;

    for (int kc = 0; kc < 2; kc++) {
        int kb0 = kc*32;
        #pragma unroll
        for (int i = 0; i < 16; i++) {
            int idx = t + i*256;
            int r = idx >> 5, kk = idx & 31;
            As[kk][r] = g_AV[(size_t)(r0+r)*DK + kb0 + kk];
            Ws[kk][r] = wo[(size_t)(c0+r)*DK + kb0 + kk];
        }
        __syncthreads();
        #pragma unroll
        for (int k = 0; k < 32; k++) {
            float4 aa = *reinterpret_cast<const float4*>(&As[k][ty*4]);
            float4 ab = *reinterpret_cast<const float4*>(&As[k][64 + ty*4]);
            float4 wa = *reinterpret_cast<const float4*>(&Ws[k][tx*4]);
            float4 wb = *reinterpret_cast<const float4*>(&Ws[k][64 + tx*4]);
            float xr[8] = {aa.x,aa.y,aa.z,aa.w, ab.x,ab.y,ab.z,ab.w};
            float wr[8] = {wa.x,wa.y,wa.z,wa.w, wb.x,wb.y,wb.z,wb.w};
            #pragma unroll
            for (int i = 0; i < 8; i++)
                #pragma unroll
                for (int j = 0; j < 8; j++)
                    acc[i][j] = fmaf(xr[i], wr[j], acc[i][j]);
        }
        __syncthreads();
    }
    float alpha = 0.2f / (1.f + __expf(-mix_p[0]));
    #pragma unroll
    for (int i = 0; i < 8; i++) {
        int r = r0 + (i < 4 ? ty*4 + i : 64 + ty*4 + (i-4));
        *reinterpret_cast<float4*>(&out[(size_t)r*DD + c0 + tx*4]) =
            make_float4(acc[i][0]*alpha, acc[i][1]*alpha, acc[i][2]*alpha, acc[i][3]*alpha);
        *reinterpret_cast<float4*>(&out[(size_t)r*DD + c0 + 64 + tx*4]) =
            make_float4(acc[i][4]*alpha, acc[i][5]*alpha, acc[i][6]*alpha, acc[i][7]*alpha);
    }
}

// ============================================================
extern "C" void kernel_launch(void* const* d_in, const int* in_sizes, int n_in,
                              void* d_out, int out_size) {
    const float* X       = (const float*)d_in[0];
    const float* w1      = (const float*)d_in[2];
    const float* b1      = (const float*)d_in[3];
    const float* w2      = (const float*)d_in[4];
    const float* b2      = (const float*)d_in[5];
    const float* wq      = (const float*)d_in[6];
    const float* wk      = (const float*)d_in[7];
    const float* wc      = (const float*)d_in[8];
    const float* bc      = (const float*)d_in[9];
    const float* step_p  = (const float*)d_in[10];
    const float* decay_p = (const float*)d_in[11];
    const float* wv      = (const float*)d_in[12];
    const float* wo      = (const float*)d_in[13];
    const float* mix_p   = (const float*)d_in[14];
    float* out = (float*)d_out;

    k1_gemm<<<BN/128, 256>>>(X, w1, b1, wv);
    k2_feat<<<BN/8, 256>>>(w2, b2, wq, wk, wc, bc);
    k3_compat<<<dim3(NN/128, NN/128, BB), 256>>>();
    for (int t = 0; t < NSTEPS; t++) {
        kA_warp<<<BN/16, 256>>>(step_p);
        kB_part<<<dim3(16, NSEG, BB), 512>>>(step_p);
        kB2<<<BN/256, 256>>>(t, decay_p);
    }
    k5_part<<<dim3(16, NS5, BB), 256>>>(step_p);
    k5red<<<BN*DK/1024, 256>>>();
    k6_out<<<dim3(DD/128, BN/128), 256>>>(wo, mix_p, out);
}